// round 13
// baseline (speedup 1.0000x reference)
#include <cuda_runtime.h>
#include <cuda_fp16.h>
#include <cstdint>
#include <math.h>

// Problem constants
static const int Bv   = 16;
static const int Sv   = 1024;
static const int Dv   = 512;
static const int DFFv = 2048;
static const int BSv  = Bv * Sv;        // 16384
static const int SDv  = Sv * Dv;        // 524288 = 2^19
static const int QS   = 1536;           // packed QKV row stride

// ---------------- scratch (device globals; no allocation allowed) ----------
__device__ __half g_xh[BSv * Dv];
__device__ __half g_qkvh[BSv * QS];       // packed q|k|v, row stride 1536
__device__ __half g_ctxh[BSv * Dv];
__device__ __half g_o1h[BSv * Dv];
__device__ __half g_ffnh[BSv * DFFv];
__device__ __half g_wqkvh[Dv * QS];       // packed weights [K=512][N=1536]
__device__ __half g_woh[Dv * Dv];
__device__ __half g_w1h[Dv * DFFv];
__device__ __half g_w2h[DFFv * Dv];
__device__ float g_bqkv[QS];              // packed bias
__device__ float g_res1[BSv * Dv];
__device__ float g_out1[BSv * Dv];
__device__ float g_res2[BSv * Dv];
__device__ float g_part1[512 * 2];
__device__ float g_part2[512 * 2];
__device__ float g_stats1[16 * 2];
__device__ float g_stats2[16 * 2];

// ---------------------------------------------------------------------------
// helpers
// ---------------------------------------------------------------------------
__device__ __forceinline__ void cp16(uint32_t dst, const void* src) {
    asm volatile("cp.async.cg.shared.global [%0], [%1], 16;"
                 :: "r"(dst), "l"(src));
}
__device__ __forceinline__ void cp_commit() {
    asm volatile("cp.async.commit_group;");
}
__device__ __forceinline__ void ldm_x4(uint32_t& r0, uint32_t& r1,
                                       uint32_t& r2, uint32_t& r3, uint32_t a) {
    asm volatile("ldmatrix.sync.aligned.m8n8.x4.shared.b16 {%0,%1,%2,%3}, [%4];"
                 : "=r"(r0), "=r"(r1), "=r"(r2), "=r"(r3) : "r"(a));
}
__device__ __forceinline__ void ldm_x4t(uint32_t& r0, uint32_t& r1,
                                        uint32_t& r2, uint32_t& r3, uint32_t a) {
    asm volatile("ldmatrix.sync.aligned.m8n8.x4.trans.shared.b16 {%0,%1,%2,%3}, [%4];"
                 : "=r"(r0), "=r"(r1), "=r"(r2), "=r"(r3) : "r"(a));
}
__device__ __forceinline__ void mma16(float* d, const uint32_t* a,
                                      uint32_t b0, uint32_t b1) {
    asm volatile(
        "mma.sync.aligned.m16n8k16.row.col.f32.f16.f16.f32 "
        "{%0,%1,%2,%3}, {%4,%5,%6,%7}, {%8,%9}, {%0,%1,%2,%3};"
        : "+f"(d[0]), "+f"(d[1]), "+f"(d[2]), "+f"(d[3])
        : "r"(a[0]), "r"(a[1]), "r"(a[2]), "r"(a[3]), "r"(b0), "r"(b1));
}
__device__ __forceinline__ uint32_t sptr(const void* p) {
    return (uint32_t)__cvta_generic_to_shared(p);
}

// ---------------------------------------------------------------------------
// fp16 tensor-core GEMM: CTA 256x128, BK=32, 256 threads (8 warps, 4(M)x2(N),
// warp tile 64x64), 3-stage cp.async pipeline, one barrier per iteration.
// 32 MMAs per 8 ldmatrix per ko16 -> 4.0 MMA/LDSM (1.5x previous), attacking
// the measured L1/LDS bandwidth wall. ~190 regs, 1 CTA/SM, 8 warps.
// FUSE: epilogue adds residual, writes fp32, per-CTA LN partials.
// ---------------------------------------------------------------------------
#define ASTG (256 * 40)            // halfs per A stage (256 rows x 32+pad)
#define BSTG (32 * 136)            // halfs per B stage
#define STG  (ASTG + BSTG)         // 14592 halfs = 29184 B
#define GEMM_SMEM (3 * STG * 2)    // 87552 B

template <int RELU, int HALF_OUT, int FUSE>
__global__ void __launch_bounds__(256, 1) gemm_h(
    const __half* __restrict__ A, const __half* __restrict__ Bw,
    const float* __restrict__ bias, float* __restrict__ Cf,
    __half* __restrict__ Ch, const float* __restrict__ Xres,
    float* __restrict__ part, int N, int K)
{
    extern __shared__ __align__(16) __half smh[];

    const int tid = threadIdx.x;
    const int lane = tid & 31, wid = tid >> 5;
    const int qid = lane >> 2, tg = lane & 3;
    const int wm = (wid & 3) * 64;          // 4 warps over M=256
    const int wn = (wid >> 2) * 64;         // 2 warps over N=128
    const int m0 = blockIdx.y * 256, n0 = blockIdx.x * 128;

    float acc[4][8][4];
#pragma unroll
    for (int mt = 0; mt < 4; mt++)
#pragma unroll
        for (int nt = 0; nt < 8; nt++)
#pragma unroll
            for (int r = 0; r < 4; r++) acc[mt][nt][r] = 0.f;

    const int lr = lane & 7;
    const int lmh = (lane >> 3) & 1;
    const int lkh = lane >> 4;

    const int a_row0 = tid >> 2,  a_seg = (tid & 3) * 8;    // 64 rows x 4 segs
    const int b_row0 = tid >> 4,  b_seg = (tid & 15) * 8;   // 16 rows x 16 segs

#define LOAD_STAGE(st, k0)                                                     \
    {                                                                          \
        __half* As_ = smh + (st) * STG;                                        \
        __half* Bs_ = smh + (st) * STG + ASTG;                                 \
        _Pragma("unroll")                                                      \
        for (int j = 0; j < 4; j++)                                            \
            cp16(sptr(As_ + (a_row0 + j * 64) * 40 + a_seg),                   \
                 A + (size_t)(m0 + a_row0 + j * 64) * K + (k0) + a_seg);       \
        _Pragma("unroll")                                                      \
        for (int j = 0; j < 2; j++)                                            \
            cp16(sptr(Bs_ + (b_row0 + j * 16) * 136 + b_seg),                  \
                 Bw + (size_t)((k0) + b_row0 + j * 16) * N + n0 + b_seg);      \
    }

    const int nk = K >> 5;
    LOAD_STAGE(0, 0);  cp_commit();
    LOAD_STAGE(1, 32); cp_commit();

    for (int it = 0; it < nk; it++) {
        const int st = it % 3;
        asm volatile("cp.async.wait_group 1;");
        __syncthreads();

        if (it + 2 < nk) {
            LOAD_STAGE((it + 2) % 3, (it + 2) * 32);
            cp_commit();
        } else {
            cp_commit();
        }

        const __half* As_ = smh + st * STG;
        const __half* Bs_ = smh + st * STG + ASTG;

#pragma unroll
        for (int ko2 = 0; ko2 < 2; ko2++) {
            const int ko = ko2 * 16;
            uint32_t af[4][4];
#pragma unroll
            for (int mt = 0; mt < 4; mt++) {
                int mrow = wm + mt * 16 + lmh * 8 + lr;
                ldm_x4(af[mt][0], af[mt][1], af[mt][2], af[mt][3],
                       sptr(As_ + mrow * 40 + ko + lkh * 8));
            }
            const int krow = ko + lmh * 8 + lr;
#pragma unroll
            for (int p = 0; p < 4; p++) {
                uint32_t b0, b1, b2, b3;
                ldm_x4t(b0, b1, b2, b3,
                        sptr(Bs_ + krow * 136 + wn + p * 16 + lkh * 8));
#pragma unroll
                for (int mt = 0; mt < 4; mt++) {
                    mma16(acc[mt][2 * p],     af[mt], b0, b1);
                    mma16(acc[mt][2 * p + 1], af[mt], b2, b3);
                }
            }
        }
    }
#undef LOAD_STAGE

    float s = 0.f, s2 = 0.f;
#pragma unroll
    for (int mt = 0; mt < 4; mt++) {
        int r_lo = m0 + wm + mt * 16 + qid;
        int r_hi = r_lo + 8;
#pragma unroll
        for (int nt = 0; nt < 8; nt++) {
            int col = n0 + wn + nt * 8 + 2 * tg;
            float bx = bias[col], by = bias[col + 1];
            float v0 = acc[mt][nt][0] + bx, v1 = acc[mt][nt][1] + by;
            float v2 = acc[mt][nt][2] + bx, v3 = acc[mt][nt][3] + by;
            if (RELU) {
                v0 = fmaxf(v0, 0.f); v1 = fmaxf(v1, 0.f);
                v2 = fmaxf(v2, 0.f); v3 = fmaxf(v3, 0.f);
            }
            if (FUSE) {
                float2 xa = *(const float2*)(Xres + (size_t)r_lo * N + col);
                float2 xb = *(const float2*)(Xres + (size_t)r_hi * N + col);
                v0 += xa.x; v1 += xa.y; v2 += xb.x; v3 += xb.y;
                s  += v0 + v1 + v2 + v3;
                s2 += v0 * v0 + v1 * v1 + v2 * v2 + v3 * v3;
            }
            if (HALF_OUT) {
                *(__half2*)(Ch + (size_t)r_lo * N + col) = __floats2half2_rn(v0, v1);
                *(__half2*)(Ch + (size_t)r_hi * N + col) = __floats2half2_rn(v2, v3);
            } else {
                *(float2*)(Cf + (size_t)r_lo * N + col) = make_float2(v0, v1);
                *(float2*)(Cf + (size_t)r_hi * N + col) = make_float2(v2, v3);
            }
        }
    }

    if (FUSE) {
        float* rsum  = (float*)smh;          // reuse stage smem
        float* rsum2 = rsum + 256;
        __syncthreads();
        rsum[tid] = s; rsum2[tid] = s2;
        __syncthreads();
        for (int off = 128; off > 0; off >>= 1) {
            if (tid < off) { rsum[tid] += rsum[tid + off]; rsum2[tid] += rsum2[tid + off]; }
            __syncthreads();
        }
        if (tid == 0) {
            int pidx = blockIdx.y * gridDim.x + blockIdx.x;
            part[2 * pidx]     = rsum[0];
            part[2 * pidx + 1] = rsum2[0];
        }
    }
}

// ---------------------------------------------------------------------------
// Single prep kernel
// ---------------------------------------------------------------------------
__global__ void __launch_bounds__(256) prep(
    const float* __restrict__ x,
    const float* __restrict__ wq, const float* __restrict__ wk,
    const float* __restrict__ wv, const float* __restrict__ wo,
    const float* __restrict__ w1, const float* __restrict__ w2,
    const float* __restrict__ bq, const float* __restrict__ bk,
    const float* __restrict__ bv,
    __half* __restrict__ xh, __half* __restrict__ wqkvh,
    __half* __restrict__ woh, __half* __restrict__ w1h,
    __half* __restrict__ w2h, float* __restrict__ bqkv)
{
    const int blk = blockIdx.x;
    const int tid = threadIdx.x;

    if (blk < 10496) {
        const float* src; __half* dst; size_t base;
        if (blk < 8192)       { src = x;  dst = xh;  base = (size_t)blk * 1024; }
        else if (blk < 8448)  { src = wo; dst = woh; base = (size_t)(blk - 8192) * 1024; }
        else if (blk < 9472)  { src = w1; dst = w1h; base = (size_t)(blk - 8448) * 1024; }
        else                  { src = w2; dst = w2h; base = (size_t)(blk - 9472) * 1024; }
        size_t i = base + (size_t)tid * 4;
        float4 v = *(const float4*)(src + i);
        *(__half2*)(dst + i)     = __floats2half2_rn(v.x, v.y);
        *(__half2*)(dst + i + 2) = __floats2half2_rn(v.z, v.w);
    } else if (blk < 11264) {
        const float* src; int off; int sb;
        if (blk < 10752)      { src = wq; off = 0;    sb = blk - 10496; }
        else if (blk < 11008) { src = wk; off = 512;  sb = blk - 10752; }
        else                  { src = wv; off = 1024; sb = blk - 11008; }
        size_t i = (size_t)sb * 1024 + (size_t)tid * 4;
        int row = (int)(i >> 9), col = (int)(i & 511);
        float4 v = *(const float4*)(src + i);
        __half* d = wqkvh + (size_t)row * QS + off + col;
        *(__half2*)(d)     = __floats2half2_rn(v.x, v.y);
        *(__half2*)(d + 2) = __floats2half2_rn(v.z, v.w);
    } else {
        for (int i = tid; i < 1536; i += 256)
            bqkv[i] = (i < 512) ? bq[i] : (i < 1024) ? bk[i - 512] : bv[i - 1024];
    }
}

// ---------------------------------------------------------------------------
// Flash attention, fp16 MMAs. grid = (S/128, B*H), block = 256 (8 warps).
// Fixed m=0 softmax; l reduced once at the end. (round-9 best, unchanged)
// ---------------------------------------------------------------------------
#define ATT_SMEM 59392

__global__ void __launch_bounds__(256) attn_h(
    const __half* __restrict__ QKV, const float* __restrict__ mask,
    __half* __restrict__ O)
{
    extern __shared__ __align__(16) char smraw[];
    __half* KsB = (__half*)smraw;                  // [2][64][72]
    __half* VsB = (__half*)(smraw + 18432);        // [2][64][72]
    __half* Psb = (__half*)(smraw + 36864);        // [128][72]
    float*  Msk = (float*)(smraw + 55296);         // [1024]

    const int tid = threadIdx.x;
    const int lane = tid & 31, wid = tid >> 5;
    const int qid = lane >> 2, tg = lane & 3;
    const int lr = lane & 7, lmh = (lane >> 3) & 1, lkh = lane >> 4;
    const int qt = blockIdx.x;
    const int b  = blockIdx.y >> 3;
    const int h  = blockIdx.y & 7;
    const size_t hcol = (size_t)h * 64;
    const size_t brow = (size_t)b * Sv;

#define LOAD_KV(st, kt)                                                        \
    {                                                                          \
        _Pragma("unroll")                                                      \
        for (int i = 0; i < 2; i++) {                                          \
            int c = tid + i * 256;                                             \
            int row = c >> 3, seg = c & 7;                                     \
            size_t g = (brow + (kt) * 64 + row) * QS + hcol + seg * 8;         \
            cp16(sptr(KsB + (st) * 4608 + row * 72 + seg * 8), QKV + g + 512); \
            cp16(sptr(VsB + (st) * 4608 + row * 72 + seg * 8), QKV + g + 1024);\
        }                                                                      \
    }

    LOAD_KV(0, 0);
    cp_commit();

#pragma unroll
    for (int i = 0; i < 4; i++)
        Msk[tid + i * 256] = mask[b * Sv + tid + i * 256] * -1e9f;

#pragma unroll
    for (int i = 0; i < 4; i++) {
        int c = tid + i * 256;
        int row = c >> 3, seg = c & 7;
        *(uint4*)(Psb + row * 72 + seg * 8) =
            *(const uint4*)(QKV + (brow + qt * 128 + row) * QS + hcol + seg * 8);
    }
    __syncthreads();

    const int rm = wid * 16 + qid;
    uint32_t qf[4][4];
#pragma unroll
    for (int kk = 0; kk < 4; kk++) {
        qf[kk][0] = *(const uint32_t*)(Psb + rm * 72 + kk * 16 + 2 * tg);
        qf[kk][1] = *(const uint32_t*)(Psb + (rm + 8) * 72 + kk * 16 + 2 * tg);
        qf[kk][2] = *(const uint32_t*)(Psb + rm * 72 + kk * 16 + 2 * tg + 8);
        qf[kk][3] = *(const uint32_t*)(Psb + (rm + 8) * 72 + kk * 16 + 2 * tg + 8);
    }

    float l_lo = 0.f, l_hi = 0.f;
    float of[8][4];
#pragma unroll
    for (int nt = 0; nt < 8; nt++)
#pragma unroll
        for (int r = 0; r < 4; r++) of[nt][r] = 0.f;

    for (int kt = 0; kt < 16; kt++) {
        const int st = kt & 1;
        asm volatile("cp.async.wait_group 0;");
        __syncthreads();
        if (kt + 1 < 16) {
            LOAD_KV(st ^ 1, kt + 1);
            cp_commit();
        }

        float sc[8][4];
#pragma unroll
        for (int nt = 0; nt < 8; nt++) {
#pragma unroll
            for (int r = 0; r < 4; r++) sc[nt][r] = 0.f;
            const __half* kr = KsB + st * 4608 + (nt * 8 + qid) * 72;
#pragma unroll
            for (int kk = 0; kk < 4; kk++) {
                uint32_t b0 = *(const uint32_t*)(kr + kk * 16 + 2 * tg);
                uint32_t b1 = *(const uint32_t*)(kr + kk * 16 + 2 * tg + 8);
                mma16(sc[nt], qf[kk], b0, b1);
            }
        }

#pragma unroll
        for (int nt = 0; nt < 8; nt++) {
            int col = kt * 64 + nt * 8 + 2 * tg;
            float mk0 = Msk[col], mk1 = Msk[col + 1];
            float e0 = __expf(sc[nt][0] * 0.125f + mk0);
            float e1 = __expf(sc[nt][1] * 0.125f + mk1);
            float e2 = __expf(sc[nt][2] * 0.125f + mk0);
            float e3 = __expf(sc[nt][3] * 0.125f + mk1);
            l_lo += e0 + e1;
            l_hi += e2 + e3;
            *(__half2*)(Psb + rm * 72 + nt * 8 + 2 * tg) =
                __floats2half2_rn(e0, e1);
            *(__half2*)(Psb + (rm + 8) * 72 + nt * 8 + 2 * tg) =
                __floats2half2_rn(e2, e3);
        }
        __syncwarp();

#pragma unroll
        for (int kk = 0; kk < 4; kk++) {
            uint32_t pa[4];
            pa[0] = *(const uint32_t*)(Psb + rm * 72 + kk * 16 + 2 * tg);
            pa[1] = *(const uint32_t*)(Psb + (rm + 8) * 72 + kk * 16 + 2 * tg);
            pa[2] = *(const uint32_t*)(Psb + rm * 72 + kk * 16 + 2 * tg + 8);
            pa[3] = *(const uint32_t*)(Psb + (rm + 8) * 72 + kk * 16 + 2 * tg + 8);
#pragma unroll
            for (int p = 0; p < 4; p++) {
                uint32_t b0, b1, b2, b3;
                int krow = kk * 16 + lmh * 8 + lr;
                int ncol = p * 16 + lkh * 8;
                ldm_x4t(b0, b1, b2, b3,
                        sptr(VsB + st * 4608 + krow * 72 + ncol));
                mma16(of[2 * p],     pa, b0, b1);
                mma16(of[2 * p + 1], pa, b2, b3);
            }
        }
    }
#undef LOAD_KV

    l_lo += __shfl_xor_sync(0xffffffffu, l_lo, 1);
    l_lo += __shfl_xor_sync(0xffffffffu, l_lo, 2);
    l_hi += __shfl_xor_sync(0xffffffffu, l_hi, 1);
    l_hi += __shfl_xor_sync(0xffffffffu, l_hi, 2);

    float inv_lo = 1.f / l_lo, inv_hi = 1.f / l_hi;
    size_t r_lo = brow + qt * 128 + rm;
    size_t r_hi = r_lo + 8;
#pragma unroll
    for (int nt = 0; nt < 8; nt++) {
        size_t col = hcol + nt * 8 + 2 * tg;
        *(__half2*)(O + r_lo * Dv + col) =
            __floats2half2_rn(of[nt][0] * inv_lo, of[nt][1] * inv_lo);
        *(__half2*)(O + r_hi * Dv + col) =
            __floats2half2_rn(of[nt][2] * inv_hi, of[nt][3] * inv_hi);
    }
}

// ---------------------------------------------------------------------------
// LayerNorm finalize: 16 partials per batch (M-tile 256 -> 4 y-blocks/batch
// x 4 x-blocks). Lanes >= 16 contribute zero.
// ---------------------------------------------------------------------------
__global__ void ln_finalize16(const float* __restrict__ part,
                              float* __restrict__ stats)
{
    const int b = blockIdx.x;
    const int t = threadIdx.x;    // 32
    float s = 0.f, s2 = 0.f;
    if (t < 16) {
        s  = part[(b * 16 + t) * 2 + 0];
        s2 = part[(b * 16 + t) * 2 + 1];
    }
#pragma unroll
    for (int m = 16; m; m >>= 1) {
        s  += __shfl_xor_sync(0xffffffffu, s, m);
        s2 += __shfl_xor_sync(0xffffffffu, s2, m);
    }
    if (t == 0) {
        float n = (float)SDv;
        float mean = s / n;
        float var  = s2 / n - mean * mean;
        stats[b * 2 + 0] = mean;
        stats[b * 2 + 1] = rsqrtf(var + 1e-5f);
    }
}

template <int HALF_COPY>
__global__ void __launch_bounds__(256) ln_apply(
    const float* __restrict__ R, const float* __restrict__ stats,
    const float* __restrict__ W, const float* __restrict__ Bb,
    float* __restrict__ out, __half* __restrict__ outh)
{
    size_t i4 = (size_t)blockIdx.x * 256 + threadIdx.x;
    size_t e  = i4 * 4;
    int b  = (int)(e >> 19);
    int sd = (int)(e & (SDv - 1));
    float mean = stats[b * 2 + 0];
    float rstd = stats[b * 2 + 1];
    float4 r  = *(const float4*)(R + e);
    float4 w4 = *(const float4*)(W + sd);
    float4 b4 = *(const float4*)(Bb + sd);
    float4 y;
    y.x = (r.x - mean) * rstd * w4.x + b4.x;
    y.y = (r.y - mean) * rstd * w4.y + b4.y;
    y.z = (r.z - mean) * rstd * w4.z + b4.z;
    y.w = (r.w - mean) * rstd * w4.w + b4.w;
    *(float4*)(out + e) = y;
    if (HALF_COPY) {
        *(__half2*)(outh + e)     = __floats2half2_rn(y.x, y.y);
        *(__half2*)(outh + e + 2) = __floats2half2_rn(y.z, y.w);
    }
}

// ---------------------------------------------------------------------------
extern "C" void kernel_launch(void* const* d_in, const int* in_sizes, int n_in,
                              void* d_out, int out_size)
{
    const float* x    = (const float*)d_in[0];
    const float* mask = (const float*)d_in[1];
    const float* wq   = (const float*)d_in[2];
    const float* bq   = (const float*)d_in[3];
    const float* wk   = (const float*)d_in[4];
    const float* bk   = (const float*)d_in[5];
    const float* wv   = (const float*)d_in[6];
    const float* bv   = (const float*)d_in[7];
    const float* wo   = (const float*)d_in[8];
    const float* bo   = (const float*)d_in[9];
    const float* w1   = (const float*)d_in[10];
    const float* b1   = (const float*)d_in[11];
    const float* w2   = (const float*)d_in[12];
    const float* b2   = (const float*)d_in[13];
    const float* ln1w = (const float*)d_in[14];
    const float* ln1b = (const float*)d_in[15];
    const float* ln2w = (const float*)d_in[16];
    const float* ln2b = (const float*)d_in[17];
    float* out = (float*)d_out;

    void* p;
    cudaGetSymbolAddress(&p, g_xh);      __half* xh    = (__half*)p;
    cudaGetSymbolAddress(&p, g_qkvh);    __half* qkvh  = (__half*)p;
    cudaGetSymbolAddress(&p, g_ctxh);    __half* ctxh  = (__half*)p;
    cudaGetSymbolAddress(&p, g_o1h);     __half* o1h   = (__half*)p;
    cudaGetSymbolAddress(&p, g_ffnh);    __half* ffnh  = (__half*)p;
    cudaGetSymbolAddress(&p, g_wqkvh);   __half* wqkvh = (__half*)p;
    cudaGetSymbolAddress(&p, g_woh);     __half* woh   = (__half*)p;
    cudaGetSymbolAddress(&p, g_w1h);     __half* w1h   = (__half*)p;
    cudaGetSymbolAddress(&p, g_w2h);     __half* w2h   = (__half*)p;
    cudaGetSymbolAddress(&p, g_bqkv);    float* bqkv   = (float*)p;
    cudaGetSymbolAddress(&p, g_res1);    float* res1   = (float*)p;
    cudaGetSymbolAddress(&p, g_out1);    float* out1   = (float*)p;
    cudaGetSymbolAddress(&p, g_res2);    float* res2   = (float*)p;
    cudaGetSymbolAddress(&p, g_part1);   float* part1  = (float*)p;
    cudaGetSymbolAddress(&p, g_part2);   float* part2  = (float*)p;
    cudaGetSymbolAddress(&p, g_stats1);  float* stats1 = (float*)p;
    cudaGetSymbolAddress(&p, g_stats2);  float* stats2 = (float*)p;

    cudaFuncSetAttribute(attn_h,
                         cudaFuncAttributeMaxDynamicSharedMemorySize, ATT_SMEM);
    cudaFuncSetAttribute(gemm_h<0, 1, 0>,
                         cudaFuncAttributeMaxDynamicSharedMemorySize, GEMM_SMEM);
    cudaFuncSetAttribute(gemm_h<0, 0, 1>,
                         cudaFuncAttributeMaxDynamicSharedMemorySize, GEMM_SMEM);
    cudaFuncSetAttribute(gemm_h<1, 1, 0>,
                         cudaFuncAttributeMaxDynamicSharedMemorySize, GEMM_SMEM);

    dim3 blk(256);
    dim3 gQKV(QS / 128, BSv / 256);    // (12, 64)
    dim3 gD(Dv / 128, BSv / 256);      // (4, 64) -> 16 partials/batch
    dim3 gF(DFFv / 128, BSv / 256);    // (16, 64)
    dim3 gAttn(Sv / 128, Bv * 8);      // (8, 128)
    int  gApply = (BSv * Dv / 4) / 256;

    prep<<<11265, 256>>>(x, wq, wk, wv, wo, w1, w2, bq, bk, bv,
                         xh, wqkvh, woh, w1h, w2h, bqkv);

    gemm_h<0, 1, 0><<<gQKV, blk, GEMM_SMEM>>>(xh, wqkvh, bqkv, nullptr, qkvh,
                                              nullptr, nullptr, QS, Dv);

    attn_h<<<gAttn, blk, ATT_SMEM>>>(qkvh, mask, ctxh);

    gemm_h<0, 0, 1><<<gD, blk, GEMM_SMEM>>>(ctxh, woh, bo, res1, nullptr,
                                            x, part1, Dv, Dv);
    ln_finalize16<<<Bv, 32>>>(part1, stats1);
    ln_apply<1><<<gApply, blk>>>(res1, stats1, ln1w, ln1b, out1, o1h);

    gemm_h<1, 1, 0><<<gF, blk, GEMM_SMEM>>>(o1h, w1h, b1, nullptr, ffnh,
                                            nullptr, nullptr, DFFv, Dv);
    gemm_h<0, 0, 1><<<gD, blk, GEMM_SMEM>>>(ffnh, w2h, b2, res2, nullptr,
                                            out1, part2, Dv, DFFv);
    ln_finalize16<<<Bv, 32>>>(part2, stats2);
    ln_apply<0><<<gApply, blk>>>(res2, stats2, ln2w, ln2b, out, nullptr);
}

// round 14
// speedup vs baseline: 1.1159x; 1.1159x over previous
#include <cuda_runtime.h>
#include <cuda_fp16.h>
#include <cstdint>
#include <math.h>

// Problem constants
static const int Bv   = 16;
static const int Sv   = 1024;
static const int Dv   = 512;
static const int DFFv = 2048;
static const int BSv  = Bv * Sv;        // 16384
static const int SDv  = Sv * Dv;        // 524288 = 2^19
static const int QS   = 1536;           // packed QKV row stride

// ---------------- scratch (device globals; no allocation allowed) ----------
__device__ __half g_xh[BSv * Dv];
__device__ __half g_qkvh[BSv * QS];       // packed q|k|v, row stride 1536
__device__ __half g_ctxh[BSv * Dv];
__device__ __half g_o1h[BSv * Dv];
__device__ __half g_ffnh[BSv * DFFv];
__device__ __half g_wqkvh[Dv * QS];       // packed weights [K=512][N=1536]
__device__ __half g_woh[Dv * Dv];
__device__ __half g_w1h[Dv * DFFv];
__device__ __half g_w2h[DFFv * Dv];
__device__ float g_bqkv[QS];              // packed bias
__device__ float g_res1[BSv * Dv];
__device__ float g_out1[BSv * Dv];
__device__ float g_res2[BSv * Dv];
__device__ float g_part1[512 * 2];
__device__ float g_part2[512 * 2];
__device__ float g_stats1[16 * 2];
__device__ float g_stats2[16 * 2];

// ---------------------------------------------------------------------------
// helpers
// ---------------------------------------------------------------------------
__device__ __forceinline__ void cp16(uint32_t dst, const void* src) {
    asm volatile("cp.async.cg.shared.global [%0], [%1], 16;"
                 :: "r"(dst), "l"(src));
}
__device__ __forceinline__ void cp_commit() {
    asm volatile("cp.async.commit_group;");
}
__device__ __forceinline__ void ldm_x4(uint32_t& r0, uint32_t& r1,
                                       uint32_t& r2, uint32_t& r3, uint32_t a) {
    asm volatile("ldmatrix.sync.aligned.m8n8.x4.shared.b16 {%0,%1,%2,%3}, [%4];"
                 : "=r"(r0), "=r"(r1), "=r"(r2), "=r"(r3) : "r"(a));
}
__device__ __forceinline__ void ldm_x4t(uint32_t& r0, uint32_t& r1,
                                        uint32_t& r2, uint32_t& r3, uint32_t a) {
    asm volatile("ldmatrix.sync.aligned.m8n8.x4.trans.shared.b16 {%0,%1,%2,%3}, [%4];"
                 : "=r"(r0), "=r"(r1), "=r"(r2), "=r"(r3) : "r"(a));
}
__device__ __forceinline__ void mma16(float* d, const uint32_t* a,
                                      uint32_t b0, uint32_t b1) {
    asm volatile(
        "mma.sync.aligned.m16n8k16.row.col.f32.f16.f16.f32 "
        "{%0,%1,%2,%3}, {%4,%5,%6,%7}, {%8,%9}, {%0,%1,%2,%3};"
        : "+f"(d[0]), "+f"(d[1]), "+f"(d[2]), "+f"(d[3])
        : "r"(a[0]), "r"(a[1]), "r"(a[2]), "r"(a[3]), "r"(b0), "r"(b1));
}
__device__ __forceinline__ uint32_t sptr(const void* p) {
    return (uint32_t)__cvta_generic_to_shared(p);
}

// ---------------------------------------------------------------------------
// fp16 tensor-core GEMM: round-9 proven config. CTA 128x128, BK=32, 256
// threads (8 warps 4x2, warp tile 32x64), 3-stage cp.async pipeline, one
// barrier per iteration, B-fragment software pipelining.
// ---------------------------------------------------------------------------
#define ASTG (128 * 40)            // halfs per A stage
#define BSTG (32 * 136)            // halfs per B stage
#define STG  (ASTG + BSTG)         // 9472 halfs = 18944 B
#define GEMM_SMEM (3 * STG * 2)    // 56832 B

template <int RELU, int HALF_OUT, int FUSE>
__global__ void __launch_bounds__(256, 2) gemm_h(
    const __half* __restrict__ A, const __half* __restrict__ Bw,
    const float* __restrict__ bias, float* __restrict__ Cf,
    __half* __restrict__ Ch, const float* __restrict__ Xres,
    float* __restrict__ part, int N, int K)
{
    extern __shared__ __align__(16) __half smh[];

    const int tid = threadIdx.x;
    const int lane = tid & 31, wid = tid >> 5;
    const int qid = lane >> 2, tg = lane & 3;
    const int wm = (wid & 3) * 32, wn = (wid >> 2) * 64;
    const int m0 = blockIdx.y * 128, n0 = blockIdx.x * 128;

    float acc[2][8][4];
#pragma unroll
    for (int mt = 0; mt < 2; mt++)
#pragma unroll
        for (int nt = 0; nt < 8; nt++)
#pragma unroll
            for (int r = 0; r < 4; r++) acc[mt][nt][r] = 0.f;

    const int lr = lane & 7;
    const int lmh = (lane >> 3) & 1;
    const int lkh = lane >> 4;

    const int a_row0 = tid >> 2,  a_seg = (tid & 3) * 8;
    const int b_row0 = tid >> 4,  b_seg = (tid & 15) * 8;

#define LOAD_STAGE(st, k0)                                                     \
    {                                                                          \
        __half* As_ = smh + (st) * STG;                                        \
        __half* Bs_ = smh + (st) * STG + ASTG;                                 \
        cp16(sptr(As_ + a_row0 * 40 + a_seg),                                  \
             A + (size_t)(m0 + a_row0) * K + (k0) + a_seg);                    \
        cp16(sptr(As_ + (a_row0 + 64) * 40 + a_seg),                           \
             A + (size_t)(m0 + a_row0 + 64) * K + (k0) + a_seg);               \
        cp16(sptr(Bs_ + b_row0 * 136 + b_seg),                                 \
             Bw + (size_t)((k0) + b_row0) * N + n0 + b_seg);                   \
        cp16(sptr(Bs_ + (b_row0 + 16) * 136 + b_seg),                          \
             Bw + (size_t)((k0) + b_row0 + 16) * N + n0 + b_seg);              \
    }

    const int nk = K >> 5;
    LOAD_STAGE(0, 0);  cp_commit();
    LOAD_STAGE(1, 32); cp_commit();

    for (int it = 0; it < nk; it++) {
        const int st = it % 3;
        asm volatile("cp.async.wait_group 1;");
        __syncthreads();

        if (it + 2 < nk) {
            LOAD_STAGE((it + 2) % 3, (it + 2) * 32);
            cp_commit();
        } else {
            cp_commit();
        }

        const __half* As_ = smh + st * STG;
        const __half* Bs_ = smh + st * STG + ASTG;

#pragma unroll
        for (int ko2 = 0; ko2 < 2; ko2++) {
            const int ko = ko2 * 16;
            uint32_t af[2][4];
#pragma unroll
            for (int mt = 0; mt < 2; mt++) {
                int mrow = wm + mt * 16 + lmh * 8 + lr;
                ldm_x4(af[mt][0], af[mt][1], af[mt][2], af[mt][3],
                       sptr(As_ + mrow * 40 + ko + lkh * 8));
            }
            const int krow = ko + lmh * 8 + lr;
            uint32_t bf[2][4];
            ldm_x4t(bf[0][0], bf[0][1], bf[0][2], bf[0][3],
                    sptr(Bs_ + krow * 136 + wn + lkh * 8));
#pragma unroll
            for (int p = 0; p < 4; p++) {
                const int cur = p & 1, nxt = cur ^ 1;
                if (p < 3)
                    ldm_x4t(bf[nxt][0], bf[nxt][1], bf[nxt][2], bf[nxt][3],
                            sptr(Bs_ + krow * 136 + wn + (p + 1) * 16 + lkh * 8));
                mma16(acc[0][2 * p],     af[0], bf[cur][0], bf[cur][1]);
                mma16(acc[1][2 * p],     af[1], bf[cur][0], bf[cur][1]);
                mma16(acc[0][2 * p + 1], af[0], bf[cur][2], bf[cur][3]);
                mma16(acc[1][2 * p + 1], af[1], bf[cur][2], bf[cur][3]);
            }
        }
    }
#undef LOAD_STAGE

    float s = 0.f, s2 = 0.f;
#pragma unroll
    for (int mt = 0; mt < 2; mt++) {
        int r_lo = m0 + wm + mt * 16 + qid;
        int r_hi = r_lo + 8;
#pragma unroll
        for (int nt = 0; nt < 8; nt++) {
            int col = n0 + wn + nt * 8 + 2 * tg;
            float bx = bias[col], by = bias[col + 1];
            float v0 = acc[mt][nt][0] + bx, v1 = acc[mt][nt][1] + by;
            float v2 = acc[mt][nt][2] + bx, v3 = acc[mt][nt][3] + by;
            if (RELU) {
                v0 = fmaxf(v0, 0.f); v1 = fmaxf(v1, 0.f);
                v2 = fmaxf(v2, 0.f); v3 = fmaxf(v3, 0.f);
            }
            if (FUSE) {
                float2 xa = *(const float2*)(Xres + (size_t)r_lo * N + col);
                float2 xb = *(const float2*)(Xres + (size_t)r_hi * N + col);
                v0 += xa.x; v1 += xa.y; v2 += xb.x; v3 += xb.y;
                s  += v0 + v1 + v2 + v3;
                s2 += v0 * v0 + v1 * v1 + v2 * v2 + v3 * v3;
            }
            if (HALF_OUT) {
                *(__half2*)(Ch + (size_t)r_lo * N + col) = __floats2half2_rn(v0, v1);
                *(__half2*)(Ch + (size_t)r_hi * N + col) = __floats2half2_rn(v2, v3);
            } else {
                *(float2*)(Cf + (size_t)r_lo * N + col) = make_float2(v0, v1);
                *(float2*)(Cf + (size_t)r_hi * N + col) = make_float2(v2, v3);
            }
        }
    }

    if (FUSE) {
        float* rsum  = (float*)smh;
        float* rsum2 = rsum + 256;
        __syncthreads();
        rsum[tid] = s; rsum2[tid] = s2;
        __syncthreads();
        for (int off = 128; off > 0; off >>= 1) {
            if (tid < off) { rsum[tid] += rsum[tid + off]; rsum2[tid] += rsum2[tid + off]; }
            __syncthreads();
        }
        if (tid == 0) {
            int pidx = blockIdx.y * gridDim.x + blockIdx.x;
            part[2 * pidx]     = rsum[0];
            part[2 * pidx + 1] = rsum2[0];
        }
    }
}

// ---------------------------------------------------------------------------
// Single prep kernel
// ---------------------------------------------------------------------------
__global__ void __launch_bounds__(256) prep(
    const float* __restrict__ x,
    const float* __restrict__ wq, const float* __restrict__ wk,
    const float* __restrict__ wv, const float* __restrict__ wo,
    const float* __restrict__ w1, const float* __restrict__ w2,
    const float* __restrict__ bq, const float* __restrict__ bk,
    const float* __restrict__ bv,
    __half* __restrict__ xh, __half* __restrict__ wqkvh,
    __half* __restrict__ woh, __half* __restrict__ w1h,
    __half* __restrict__ w2h, float* __restrict__ bqkv)
{
    const int blk = blockIdx.x;
    const int tid = threadIdx.x;

    if (blk < 10496) {
        const float* src; __half* dst; size_t base;
        if (blk < 8192)       { src = x;  dst = xh;  base = (size_t)blk * 1024; }
        else if (blk < 8448)  { src = wo; dst = woh; base = (size_t)(blk - 8192) * 1024; }
        else if (blk < 9472)  { src = w1; dst = w1h; base = (size_t)(blk - 8448) * 1024; }
        else                  { src = w2; dst = w2h; base = (size_t)(blk - 9472) * 1024; }
        size_t i = base + (size_t)tid * 4;
        float4 v = *(const float4*)(src + i);
        *(__half2*)(dst + i)     = __floats2half2_rn(v.x, v.y);
        *(__half2*)(dst + i + 2) = __floats2half2_rn(v.z, v.w);
    } else if (blk < 11264) {
        const float* src; int off; int sb;
        if (blk < 10752)      { src = wq; off = 0;    sb = blk - 10496; }
        else if (blk < 11008) { src = wk; off = 512;  sb = blk - 10752; }
        else                  { src = wv; off = 1024; sb = blk - 11008; }
        size_t i = (size_t)sb * 1024 + (size_t)tid * 4;
        int row = (int)(i >> 9), col = (int)(i & 511);
        float4 v = *(const float4*)(src + i);
        __half* d = wqkvh + (size_t)row * QS + off + col;
        *(__half2*)(d)     = __floats2half2_rn(v.x, v.y);
        *(__half2*)(d + 2) = __floats2half2_rn(v.z, v.w);
    } else {
        for (int i = tid; i < 1536; i += 256)
            bqkv[i] = (i < 512) ? bq[i] : (i < 1024) ? bk[i - 512] : bv[i - 1024];
    }
}

// ---------------------------------------------------------------------------
// Flash attention, fp16 MMAs. grid = (S/128, B*H), block = 256 (8 warps).
// Fixed m=0 softmax; l reduced once at the end.
// THIS ROUND: all K and P fragments loaded via ldmatrix.x4 (was 80 scalar
// LDS.32 per tile -> 20 ldmatrix), cutting mainloop issue pressure.
// ---------------------------------------------------------------------------
#define ATT_SMEM 59392

__global__ void __launch_bounds__(256) attn_h(
    const __half* __restrict__ QKV, const float* __restrict__ mask,
    __half* __restrict__ O)
{
    extern __shared__ __align__(16) char smraw[];
    __half* KsB = (__half*)smraw;                  // [2][64][72]
    __half* VsB = (__half*)(smraw + 18432);        // [2][64][72]
    __half* Psb = (__half*)(smraw + 36864);        // [128][72]
    float*  Msk = (float*)(smraw + 55296);         // [1024]

    const int tid = threadIdx.x;
    const int lane = tid & 31, wid = tid >> 5;
    const int qid = lane >> 2, tg = lane & 3;
    const int lr = lane & 7, lg = lane >> 3;       // lane group 0..3
    const int lmh = lg & 1, lkh = lane >> 4;
    const int qt = blockIdx.x;
    const int b  = blockIdx.y >> 3;
    const int h  = blockIdx.y & 7;
    const size_t hcol = (size_t)h * 64;
    const size_t brow = (size_t)b * Sv;

#define LOAD_KV(st, kt)                                                        \
    {                                                                          \
        _Pragma("unroll")                                                      \
        for (int i = 0; i < 2; i++) {                                          \
            int c = tid + i * 256;                                             \
            int row = c >> 3, seg = c & 7;                                     \
            size_t g = (brow + (kt) * 64 + row) * QS + hcol + seg * 8;         \
            cp16(sptr(KsB + (st) * 4608 + row * 72 + seg * 8), QKV + g + 512); \
            cp16(sptr(VsB + (st) * 4608 + row * 72 + seg * 8), QKV + g + 1024);\
        }                                                                      \
    }

    LOAD_KV(0, 0);
    cp_commit();

#pragma unroll
    for (int i = 0; i < 4; i++)
        Msk[tid + i * 256] = mask[b * Sv + tid + i * 256] * -1e9f;

#pragma unroll
    for (int i = 0; i < 4; i++) {
        int c = tid + i * 256;
        int row = c >> 3, seg = c & 7;
        *(uint4*)(Psb + row * 72 + seg * 8) =
            *(const uint4*)(QKV + (brow + qt * 128 + row) * QS + hcol + seg * 8);
    }
    __syncthreads();

    const int rm = wid * 16 + qid;
    // Q A-fragments via ldmatrix.x4 (per kk): rows wid*16 + (lg&1)*8 + lr,
    // col kk*16 + (lg>=2)*8
    uint32_t qf[4][4];
    {
        const int qrow = wid * 16 + (lg & 1) * 8 + lr;
        const int qcol = (lg >> 1) * 8;
#pragma unroll
        for (int kk = 0; kk < 4; kk++)
            ldm_x4(qf[kk][0], qf[kk][1], qf[kk][2], qf[kk][3],
                   sptr(Psb + qrow * 72 + kk * 16 + qcol));
    }

    float l_lo = 0.f, l_hi = 0.f;
    float of[8][4];
#pragma unroll
    for (int nt = 0; nt < 8; nt++)
#pragma unroll
        for (int r = 0; r < 4; r++) of[nt][r] = 0.f;

    // lane pointer pieces for K B-frag ldmatrix (pairs of nt):
    //   row = np*16 + (lg>=2)*8 + lr ; col = kk*16 + (lg&1)*8
    const int krow_off = (lg >> 1) * 8 + lr;
    const int kcol_off = (lg & 1) * 8;
    // P A-frag ldmatrix: row = wid*16 + (lg&1)*8 + lr ; col = kk*16 + (lg>=2)*8
    const int prow = wid * 16 + (lg & 1) * 8 + lr;
    const int pcol = (lg >> 1) * 8;

    for (int kt = 0; kt < 16; kt++) {
        const int st = kt & 1;
        asm volatile("cp.async.wait_group 0;");
        __syncthreads();
        if (kt + 1 < 16) {
            LOAD_KV(st ^ 1, kt + 1);
            cp_commit();
        }

        // S = Q @ K^T  — K B-frags via ldmatrix.x4 (2 nt per load)
        float sc[8][4];
#pragma unroll
        for (int nt = 0; nt < 8; nt++)
#pragma unroll
            for (int r = 0; r < 4; r++) sc[nt][r] = 0.f;

        const __half* Kb = KsB + st * 4608;
#pragma unroll
        for (int kk = 0; kk < 4; kk++) {
#pragma unroll
            for (int np = 0; np < 4; np++) {
                uint32_t b0, b1, b2, b3;
                ldm_x4(b0, b1, b2, b3,
                       sptr(Kb + (np * 16 + krow_off) * 72 + kk * 16 + kcol_off));
                mma16(sc[2 * np],     qf[kk], b0, b1);
                mma16(sc[2 * np + 1], qf[kk], b2, b3);
            }
        }

#pragma unroll
        for (int nt = 0; nt < 8; nt++) {
            int col = kt * 64 + nt * 8 + 2 * tg;
            float mk0 = Msk[col], mk1 = Msk[col + 1];
            float e0 = __expf(sc[nt][0] * 0.125f + mk0);
            float e1 = __expf(sc[nt][1] * 0.125f + mk1);
            float e2 = __expf(sc[nt][2] * 0.125f + mk0);
            float e3 = __expf(sc[nt][3] * 0.125f + mk1);
            l_lo += e0 + e1;
            l_hi += e2 + e3;
            *(__half2*)(Psb + rm * 72 + nt * 8 + 2 * tg) =
                __floats2half2_rn(e0, e1);
            *(__half2*)(Psb + (rm + 8) * 72 + nt * 8 + 2 * tg) =
                __floats2half2_rn(e2, e3);
        }
        __syncwarp();

        // O += P @ V — P A-frags via ldmatrix.x4
#pragma unroll
        for (int kk = 0; kk < 4; kk++) {
            uint32_t pa[4];
            ldm_x4(pa[0], pa[1], pa[2], pa[3],
                   sptr(Psb + prow * 72 + kk * 16 + pcol));
#pragma unroll
            for (int p = 0; p < 4; p++) {
                uint32_t b0, b1, b2, b3;
                int krow = kk * 16 + lmh * 8 + lr;
                int ncol = p * 16 + lkh * 8;
                ldm_x4t(b0, b1, b2, b3,
                        sptr(VsB + st * 4608 + krow * 72 + ncol));
                mma16(of[2 * p],     pa, b0, b1);
                mma16(of[2 * p + 1], pa, b2, b3);
            }
        }
    }
#undef LOAD_KV

    l_lo += __shfl_xor_sync(0xffffffffu, l_lo, 1);
    l_lo += __shfl_xor_sync(0xffffffffu, l_lo, 2);
    l_hi += __shfl_xor_sync(0xffffffffu, l_hi, 1);
    l_hi += __shfl_xor_sync(0xffffffffu, l_hi, 2);

    float inv_lo = 1.f / l_lo, inv_hi = 1.f / l_hi;
    size_t r_lo = brow + qt * 128 + rm;
    size_t r_hi = r_lo + 8;
#pragma unroll
    for (int nt = 0; nt < 8; nt++) {
        size_t col = hcol + nt * 8 + 2 * tg;
        *(__half2*)(O + r_lo * Dv + col) =
            __floats2half2_rn(of[nt][0] * inv_lo, of[nt][1] * inv_lo);
        *(__half2*)(O + r_hi * Dv + col) =
            __floats2half2_rn(of[nt][2] * inv_hi, of[nt][3] * inv_hi);
    }
}

// ---------------------------------------------------------------------------
// LayerNorm finalize (32 partials per batch) + apply
// ---------------------------------------------------------------------------
__global__ void ln_finalize32(const float* __restrict__ part,
                              float* __restrict__ stats)
{
    const int b = blockIdx.x;
    const int t = threadIdx.x;    // 32
    float s  = part[(b * 32 + t) * 2 + 0];
    float s2 = part[(b * 32 + t) * 2 + 1];
#pragma unroll
    for (int m = 16; m; m >>= 1) {
        s  += __shfl_xor_sync(0xffffffffu, s, m);
        s2 += __shfl_xor_sync(0xffffffffu, s2, m);
    }
    if (t == 0) {
        float n = (float)SDv;
        float mean = s / n;
        float var  = s2 / n - mean * mean;
        stats[b * 2 + 0] = mean;
        stats[b * 2 + 1] = rsqrtf(var + 1e-5f);
    }
}

template <int HALF_COPY>
__global__ void __launch_bounds__(256) ln_apply(
    const float* __restrict__ R, const float* __restrict__ stats,
    const float* __restrict__ W, const float* __restrict__ Bb,
    float* __restrict__ out, __half* __restrict__ outh)
{
    size_t i4 = (size_t)blockIdx.x * 256 + threadIdx.x;
    size_t e  = i4 * 4;
    int b  = (int)(e >> 19);
    int sd = (int)(e & (SDv - 1));
    float mean = stats[b * 2 + 0];
    float rstd = stats[b * 2 + 1];
    float4 r  = *(const float4*)(R + e);
    float4 w4 = *(const float4*)(W + sd);
    float4 b4 = *(const float4*)(Bb + sd);
    float4 y;
    y.x = (r.x - mean) * rstd * w4.x + b4.x;
    y.y = (r.y - mean) * rstd * w4.y + b4.y;
    y.z = (r.z - mean) * rstd * w4.z + b4.z;
    y.w = (r.w - mean) * rstd * w4.w + b4.w;
    *(float4*)(out + e) = y;
    if (HALF_COPY) {
        *(__half2*)(outh + e)     = __floats2half2_rn(y.x, y.y);
        *(__half2*)(outh + e + 2) = __floats2half2_rn(y.z, y.w);
    }
}

// ---------------------------------------------------------------------------
extern "C" void kernel_launch(void* const* d_in, const int* in_sizes, int n_in,
                              void* d_out, int out_size)
{
    const float* x    = (const float*)d_in[0];
    const float* mask = (const float*)d_in[1];
    const float* wq   = (const float*)d_in[2];
    const float* bq   = (const float*)d_in[3];
    const float* wk   = (const float*)d_in[4];
    const float* bk   = (const float*)d_in[5];
    const float* wv   = (const float*)d_in[6];
    const float* bv   = (const float*)d_in[7];
    const float* wo   = (const float*)d_in[8];
    const float* bo   = (const float*)d_in[9];
    const float* w1   = (const float*)d_in[10];
    const float* b1   = (const float*)d_in[11];
    const float* w2   = (const float*)d_in[12];
    const float* b2   = (const float*)d_in[13];
    const float* ln1w = (const float*)d_in[14];
    const float* ln1b = (const float*)d_in[15];
    const float* ln2w = (const float*)d_in[16];
    const float* ln2b = (const float*)d_in[17];
    float* out = (float*)d_out;

    void* p;
    cudaGetSymbolAddress(&p, g_xh);      __half* xh    = (__half*)p;
    cudaGetSymbolAddress(&p, g_qkvh);    __half* qkvh  = (__half*)p;
    cudaGetSymbolAddress(&p, g_ctxh);    __half* ctxh  = (__half*)p;
    cudaGetSymbolAddress(&p, g_o1h);     __half* o1h   = (__half*)p;
    cudaGetSymbolAddress(&p, g_ffnh);    __half* ffnh  = (__half*)p;
    cudaGetSymbolAddress(&p, g_wqkvh);   __half* wqkvh = (__half*)p;
    cudaGetSymbolAddress(&p, g_woh);     __half* woh   = (__half*)p;
    cudaGetSymbolAddress(&p, g_w1h);     __half* w1h   = (__half*)p;
    cudaGetSymbolAddress(&p, g_w2h);     __half* w2h   = (__half*)p;
    cudaGetSymbolAddress(&p, g_bqkv);    float* bqkv   = (float*)p;
    cudaGetSymbolAddress(&p, g_res1);    float* res1   = (float*)p;
    cudaGetSymbolAddress(&p, g_out1);    float* out1   = (float*)p;
    cudaGetSymbolAddress(&p, g_res2);    float* res2   = (float*)p;
    cudaGetSymbolAddress(&p, g_part1);   float* part1  = (float*)p;
    cudaGetSymbolAddress(&p, g_part2);   float* part2  = (float*)p;
    cudaGetSymbolAddress(&p, g_stats1);  float* stats1 = (float*)p;
    cudaGetSymbolAddress(&p, g_stats2);  float* stats2 = (float*)p;

    cudaFuncSetAttribute(attn_h,
                         cudaFuncAttributeMaxDynamicSharedMemorySize, ATT_SMEM);
    cudaFuncSetAttribute(gemm_h<0, 1, 0>,
                         cudaFuncAttributeMaxDynamicSharedMemorySize, GEMM_SMEM);
    cudaFuncSetAttribute(gemm_h<0, 0, 1>,
                         cudaFuncAttributeMaxDynamicSharedMemorySize, GEMM_SMEM);
    cudaFuncSetAttribute(gemm_h<1, 1, 0>,
                         cudaFuncAttributeMaxDynamicSharedMemorySize, GEMM_SMEM);

    dim3 blk(256);
    dim3 gQKV(QS / 128, BSv / 128);    // (12, 128)
    dim3 gD(Dv / 128, BSv / 128);      // (4, 128)
    dim3 gF(DFFv / 128, BSv / 128);    // (16, 128)
    dim3 gAttn(Sv / 128, Bv * 8);      // (8, 128)
    int  gApply = (BSv * Dv / 4) / 256;

    prep<<<11265, 256>>>(x, wq, wk, wv, wo, w1, w2, bq, bk, bv,
                         xh, wqkvh, woh, w1h, w2h, bqkv);

    gemm_h<0, 1, 0><<<gQKV, blk, GEMM_SMEM>>>(xh, wqkvh, bqkv, nullptr, qkvh,
                                              nullptr, nullptr, QS, Dv);

    attn_h<<<gAttn, blk, ATT_SMEM>>>(qkvh, mask, ctxh);

    gemm_h<0, 0, 1><<<gD, blk, GEMM_SMEM>>>(ctxh, woh, bo, res1, nullptr,
                                            x, part1, Dv, Dv);
    ln_finalize32<<<Bv, 32>>>(part1, stats1);
    ln_apply<1><<<gApply, blk>>>(res1, stats1, ln1w, ln1b, out1, o1h);

    gemm_h<1, 1, 0><<<gF, blk, GEMM_SMEM>>>(o1h, w1h, b1, nullptr, ffnh,
                                            nullptr, nullptr, DFFv, Dv);
    gemm_h<0, 0, 1><<<gD, blk, GEMM_SMEM>>>(ffnh, w2h, b2, res2, nullptr,
                                            out1, part2, Dv, DFFv);
    ln_finalize32<<<Bv, 32>>>(part2, stats2);
    ln_apply<0><<<gApply, blk>>>(res2, stats2, ln2w, ln2b, out, nullptr);
}

// round 15
// speedup vs baseline: 1.1317x; 1.0142x over previous
#include <cuda_runtime.h>
#include <cuda_fp16.h>
#include <cstdint>
#include <math.h>

// Problem constants
static const int Bv   = 16;
static const int Sv   = 1024;
static const int Dv   = 512;
static const int DFFv = 2048;
static const int BSv  = Bv * Sv;        // 16384
static const int SDv  = Sv * Dv;        // 524288 = 2^19
static const int QS   = 1536;           // packed QKV row stride

// ---------------- scratch (device globals; no allocation allowed) ----------
__device__ __half g_xh[BSv * Dv];
__device__ __half g_qkvh[BSv * QS];       // packed q|k|v, row stride 1536
__device__ __half g_ctxh[BSv * Dv];
__device__ __half g_o1h[BSv * Dv];
__device__ __half g_ffnh[BSv * DFFv];
__device__ __half g_res1h[BSv * Dv];
__device__ __half g_res2h[BSv * Dv];
__device__ __half g_wqkvh[Dv * QS];       // packed weights [K=512][N=1536]
__device__ __half g_woh[Dv * Dv];
__device__ __half g_w1h[Dv * DFFv];
__device__ __half g_w2h[DFFv * Dv];
__device__ float g_bqkv[QS];              // packed bias
__device__ float g_part1[512 * 2];
__device__ float g_part2[512 * 2];
__device__ float g_stats1[16 * 2];
__device__ float g_stats2[16 * 2];

// ---------------------------------------------------------------------------
// helpers
// ---------------------------------------------------------------------------
__device__ __forceinline__ void cp16(uint32_t dst, const void* src) {
    asm volatile("cp.async.cg.shared.global [%0], [%1], 16;"
                 :: "r"(dst), "l"(src));
}
__device__ __forceinline__ void cp_commit() {
    asm volatile("cp.async.commit_group;");
}
__device__ __forceinline__ void ldm_x4(uint32_t& r0, uint32_t& r1,
                                       uint32_t& r2, uint32_t& r3, uint32_t a) {
    asm volatile("ldmatrix.sync.aligned.m8n8.x4.shared.b16 {%0,%1,%2,%3}, [%4];"
                 : "=r"(r0), "=r"(r1), "=r"(r2), "=r"(r3) : "r"(a));
}
__device__ __forceinline__ void ldm_x4t(uint32_t& r0, uint32_t& r1,
                                        uint32_t& r2, uint32_t& r3, uint32_t a) {
    asm volatile("ldmatrix.sync.aligned.m8n8.x4.trans.shared.b16 {%0,%1,%2,%3}, [%4];"
                 : "=r"(r0), "=r"(r1), "=r"(r2), "=r"(r3) : "r"(a));
}
__device__ __forceinline__ void mma16(float* d, const uint32_t* a,
                                      uint32_t b0, uint32_t b1) {
    asm volatile(
        "mma.sync.aligned.m16n8k16.row.col.f32.f16.f16.f32 "
        "{%0,%1,%2,%3}, {%4,%5,%6,%7}, {%8,%9}, {%0,%1,%2,%3};"
        : "+f"(d[0]), "+f"(d[1]), "+f"(d[2]), "+f"(d[3])
        : "r"(a[0]), "r"(a[1]), "r"(a[2]), "r"(a[3]), "r"(b0), "r"(b1));
}
__device__ __forceinline__ uint32_t sptr(const void* p) {
    return (uint32_t)__cvta_generic_to_shared(p);
}

// ---------------------------------------------------------------------------
// fp16 tensor-core GEMM: round-9/14 proven config. CTA 128x128, BK=32, 256
// threads (8 warps 4x2, warp tile 32x64), 3-stage cp.async pipeline, one
// barrier per iteration, B-fragment software pipelining.
// FUSE: epilogue adds residual (fp32 ptr Xres or half ptr Xresh per XHALF),
// computes LN partials from exact fp32 values, writes result as HALF to Ch.
// ---------------------------------------------------------------------------
#define ASTG (128 * 40)            // halfs per A stage
#define BSTG (32 * 136)            // halfs per B stage
#define STG  (ASTG + BSTG)         // 9472 halfs = 18944 B
#define GEMM_SMEM (3 * STG * 2)    // 56832 B

template <int RELU, int FUSE, int XHALF>
__global__ void __launch_bounds__(256, 2) gemm_h(
    const __half* __restrict__ A, const __half* __restrict__ Bw,
    const float* __restrict__ bias, __half* __restrict__ Ch,
    const float* __restrict__ Xres, const __half* __restrict__ Xresh,
    float* __restrict__ part, int N, int K)
{
    extern __shared__ __align__(16) __half smh[];

    const int tid = threadIdx.x;
    const int lane = tid & 31, wid = tid >> 5;
    const int qid = lane >> 2, tg = lane & 3;
    const int wm = (wid & 3) * 32, wn = (wid >> 2) * 64;
    const int m0 = blockIdx.y * 128, n0 = blockIdx.x * 128;

    float acc[2][8][4];
#pragma unroll
    for (int mt = 0; mt < 2; mt++)
#pragma unroll
        for (int nt = 0; nt < 8; nt++)
#pragma unroll
            for (int r = 0; r < 4; r++) acc[mt][nt][r] = 0.f;

    const int lr = lane & 7;
    const int lmh = (lane >> 3) & 1;
    const int lkh = lane >> 4;

    const int a_row0 = tid >> 2,  a_seg = (tid & 3) * 8;
    const int b_row0 = tid >> 4,  b_seg = (tid & 15) * 8;

#define LOAD_STAGE(st, k0)                                                     \
    {                                                                          \
        __half* As_ = smh + (st) * STG;                                        \
        __half* Bs_ = smh + (st) * STG + ASTG;                                 \
        cp16(sptr(As_ + a_row0 * 40 + a_seg),                                  \
             A + (size_t)(m0 + a_row0) * K + (k0) + a_seg);                    \
        cp16(sptr(As_ + (a_row0 + 64) * 40 + a_seg),                           \
             A + (size_t)(m0 + a_row0 + 64) * K + (k0) + a_seg);               \
        cp16(sptr(Bs_ + b_row0 * 136 + b_seg),                                 \
             Bw + (size_t)((k0) + b_row0) * N + n0 + b_seg);                   \
        cp16(sptr(Bs_ + (b_row0 + 16) * 136 + b_seg),                          \
             Bw + (size_t)((k0) + b_row0 + 16) * N + n0 + b_seg);              \
    }

    const int nk = K >> 5;
    LOAD_STAGE(0, 0);  cp_commit();
    LOAD_STAGE(1, 32); cp_commit();

    for (int it = 0; it < nk; it++) {
        const int st = it % 3;
        asm volatile("cp.async.wait_group 1;");
        __syncthreads();

        if (it + 2 < nk) {
            LOAD_STAGE((it + 2) % 3, (it + 2) * 32);
            cp_commit();
        } else {
            cp_commit();
        }

        const __half* As_ = smh + st * STG;
        const __half* Bs_ = smh + st * STG + ASTG;

#pragma unroll
        for (int ko2 = 0; ko2 < 2; ko2++) {
            const int ko = ko2 * 16;
            uint32_t af[2][4];
#pragma unroll
            for (int mt = 0; mt < 2; mt++) {
                int mrow = wm + mt * 16 + lmh * 8 + lr;
                ldm_x4(af[mt][0], af[mt][1], af[mt][2], af[mt][3],
                       sptr(As_ + mrow * 40 + ko + lkh * 8));
            }
            const int krow = ko + lmh * 8 + lr;
            uint32_t bf[2][4];
            ldm_x4t(bf[0][0], bf[0][1], bf[0][2], bf[0][3],
                    sptr(Bs_ + krow * 136 + wn + lkh * 8));
#pragma unroll
            for (int p = 0; p < 4; p++) {
                const int cur = p & 1, nxt = cur ^ 1;
                if (p < 3)
                    ldm_x4t(bf[nxt][0], bf[nxt][1], bf[nxt][2], bf[nxt][3],
                            sptr(Bs_ + krow * 136 + wn + (p + 1) * 16 + lkh * 8));
                mma16(acc[0][2 * p],     af[0], bf[cur][0], bf[cur][1]);
                mma16(acc[1][2 * p],     af[1], bf[cur][0], bf[cur][1]);
                mma16(acc[0][2 * p + 1], af[0], bf[cur][2], bf[cur][3]);
                mma16(acc[1][2 * p + 1], af[1], bf[cur][2], bf[cur][3]);
            }
        }
    }
#undef LOAD_STAGE

    float s = 0.f, s2 = 0.f;
#pragma unroll
    for (int mt = 0; mt < 2; mt++) {
        int r_lo = m0 + wm + mt * 16 + qid;
        int r_hi = r_lo + 8;
#pragma unroll
        for (int nt = 0; nt < 8; nt++) {
            int col = n0 + wn + nt * 8 + 2 * tg;
            float bx = bias[col], by = bias[col + 1];
            float v0 = acc[mt][nt][0] + bx, v1 = acc[mt][nt][1] + by;
            float v2 = acc[mt][nt][2] + bx, v3 = acc[mt][nt][3] + by;
            if (RELU) {
                v0 = fmaxf(v0, 0.f); v1 = fmaxf(v1, 0.f);
                v2 = fmaxf(v2, 0.f); v3 = fmaxf(v3, 0.f);
            }
            if (FUSE) {
                if (XHALF) {
                    __half2 xa = *(const __half2*)(Xresh + (size_t)r_lo * N + col);
                    __half2 xb = *(const __half2*)(Xresh + (size_t)r_hi * N + col);
                    v0 += __low2float(xa);  v1 += __high2float(xa);
                    v2 += __low2float(xb);  v3 += __high2float(xb);
                } else {
                    float2 xa = *(const float2*)(Xres + (size_t)r_lo * N + col);
                    float2 xb = *(const float2*)(Xres + (size_t)r_hi * N + col);
                    v0 += xa.x; v1 += xa.y; v2 += xb.x; v3 += xb.y;
                }
                s  += v0 + v1 + v2 + v3;
                s2 += v0 * v0 + v1 * v1 + v2 * v2 + v3 * v3;
            }
            *(__half2*)(Ch + (size_t)r_lo * N + col) = __floats2half2_rn(v0, v1);
            *(__half2*)(Ch + (size_t)r_hi * N + col) = __floats2half2_rn(v2, v3);
        }
    }

    if (FUSE) {
        float* rsum  = (float*)smh;
        float* rsum2 = rsum + 256;
        __syncthreads();
        rsum[tid] = s; rsum2[tid] = s2;
        __syncthreads();
        for (int off = 128; off > 0; off >>= 1) {
            if (tid < off) { rsum[tid] += rsum[tid + off]; rsum2[tid] += rsum2[tid + off]; }
            __syncthreads();
        }
        if (tid == 0) {
            int pidx = blockIdx.y * gridDim.x + blockIdx.x;
            part[2 * pidx]     = rsum[0];
            part[2 * pidx + 1] = rsum2[0];
        }
    }
}

// ---------------------------------------------------------------------------
// Single prep kernel
// ---------------------------------------------------------------------------
__global__ void __launch_bounds__(256) prep(
    const float* __restrict__ x,
    const float* __restrict__ wq, const float* __restrict__ wk,
    const float* __restrict__ wv, const float* __restrict__ wo,
    const float* __restrict__ w1, const float* __restrict__ w2,
    const float* __restrict__ bq, const float* __restrict__ bk,
    const float* __restrict__ bv,
    __half* __restrict__ xh, __half* __restrict__ wqkvh,
    __half* __restrict__ woh, __half* __restrict__ w1h,
    __half* __restrict__ w2h, float* __restrict__ bqkv)
{
    const int blk = blockIdx.x;
    const int tid = threadIdx.x;

    if (blk < 10496) {
        const float* src; __half* dst; size_t base;
        if (blk < 8192)       { src = x;  dst = xh;  base = (size_t)blk * 1024; }
        else if (blk < 8448)  { src = wo; dst = woh; base = (size_t)(blk - 8192) * 1024; }
        else if (blk < 9472)  { src = w1; dst = w1h; base = (size_t)(blk - 8448) * 1024; }
        else                  { src = w2; dst = w2h; base = (size_t)(blk - 9472) * 1024; }
        size_t i = base + (size_t)tid * 4;
        float4 v = *(const float4*)(src + i);
        *(__half2*)(dst + i)     = __floats2half2_rn(v.x, v.y);
        *(__half2*)(dst + i + 2) = __floats2half2_rn(v.z, v.w);
    } else if (blk < 11264) {
        const float* src; int off; int sb;
        if (blk < 10752)      { src = wq; off = 0;    sb = blk - 10496; }
        else if (blk < 11008) { src = wk; off = 512;  sb = blk - 10752; }
        else                  { src = wv; off = 1024; sb = blk - 11008; }
        size_t i = (size_t)sb * 1024 + (size_t)tid * 4;
        int row = (int)(i >> 9), col = (int)(i & 511);
        float4 v = *(const float4*)(src + i);
        __half* d = wqkvh + (size_t)row * QS + off + col;
        *(__half2*)(d)     = __floats2half2_rn(v.x, v.y);
        *(__half2*)(d + 2) = __floats2half2_rn(v.z, v.w);
    } else {
        for (int i = tid; i < 1536; i += 256)
            bqkv[i] = (i < 512) ? bq[i] : (i < 1024) ? bk[i - 512] : bv[i - 1024];
    }
}

// ---------------------------------------------------------------------------
// Flash attention, fp16 MMAs. grid = (S/128, B*H), block = 256 (8 warps).
// Fixed m=0 softmax; l reduced once at the end; all K/P fragments via
// ldmatrix.x4. (round-14 best, unchanged)
// ---------------------------------------------------------------------------
#define ATT_SMEM 59392

__global__ void __launch_bounds__(256) attn_h(
    const __half* __restrict__ QKV, const float* __restrict__ mask,
    __half* __restrict__ O)
{
    extern __shared__ __align__(16) char smraw[];
    __half* KsB = (__half*)smraw;                  // [2][64][72]
    __half* VsB = (__half*)(smraw + 18432);        // [2][64][72]
    __half* Psb = (__half*)(smraw + 36864);        // [128][72]
    float*  Msk = (float*)(smraw + 55296);         // [1024]

    const int tid = threadIdx.x;
    const int lane = tid & 31, wid = tid >> 5;
    const int qid = lane >> 2, tg = lane & 3;
    const int lr = lane & 7, lg = lane >> 3;
    const int lmh = lg & 1, lkh = lane >> 4;
    const int qt = blockIdx.x;
    const int b  = blockIdx.y >> 3;
    const int h  = blockIdx.y & 7;
    const size_t hcol = (size_t)h * 64;
    const size_t brow = (size_t)b * Sv;

#define LOAD_KV(st, kt)                                                        \
    {                                                                          \
        _Pragma("unroll")                                                      \
        for (int i = 0; i < 2; i++) {                                          \
            int c = tid + i * 256;                                             \
            int row = c >> 3, seg = c & 7;                                     \
            size_t g = (brow + (kt) * 64 + row) * QS + hcol + seg * 8;         \
            cp16(sptr(KsB + (st) * 4608 + row * 72 + seg * 8), QKV + g + 512); \
            cp16(sptr(VsB + (st) * 4608 + row * 72 + seg * 8), QKV + g + 1024);\
        }                                                                      \
    }

    LOAD_KV(0, 0);
    cp_commit();

#pragma unroll
    for (int i = 0; i < 4; i++)
        Msk[tid + i * 256] = mask[b * Sv + tid + i * 256] * -1e9f;

#pragma unroll
    for (int i = 0; i < 4; i++) {
        int c = tid + i * 256;
        int row = c >> 3, seg = c & 7;
        *(uint4*)(Psb + row * 72 + seg * 8) =
            *(const uint4*)(QKV + (brow + qt * 128 + row) * QS + hcol + seg * 8);
    }
    __syncthreads();

    const int rm = wid * 16 + qid;
    uint32_t qf[4][4];
    {
        const int qrow = wid * 16 + (lg & 1) * 8 + lr;
        const int qcol = (lg >> 1) * 8;
#pragma unroll
        for (int kk = 0; kk < 4; kk++)
            ldm_x4(qf[kk][0], qf[kk][1], qf[kk][2], qf[kk][3],
                   sptr(Psb + qrow * 72 + kk * 16 + qcol));
    }

    float l_lo = 0.f, l_hi = 0.f;
    float of[8][4];
#pragma unroll
    for (int nt = 0; nt < 8; nt++)
#pragma unroll
        for (int r = 0; r < 4; r++) of[nt][r] = 0.f;

    const int krow_off = (lg >> 1) * 8 + lr;
    const int kcol_off = (lg & 1) * 8;
    const int prow = wid * 16 + (lg & 1) * 8 + lr;
    const int pcol = (lg >> 1) * 8;

    for (int kt = 0; kt < 16; kt++) {
        const int st = kt & 1;
        asm volatile("cp.async.wait_group 0;");
        __syncthreads();
        if (kt + 1 < 16) {
            LOAD_KV(st ^ 1, kt + 1);
            cp_commit();
        }

        float sc[8][4];
#pragma unroll
        for (int nt = 0; nt < 8; nt++)
#pragma unroll
            for (int r = 0; r < 4; r++) sc[nt][r] = 0.f;

        const __half* Kb = KsB + st * 4608;
#pragma unroll
        for (int kk = 0; kk < 4; kk++) {
#pragma unroll
            for (int np = 0; np < 4; np++) {
                uint32_t b0, b1, b2, b3;
                ldm_x4(b0, b1, b2, b3,
                       sptr(Kb + (np * 16 + krow_off) * 72 + kk * 16 + kcol_off));
                mma16(sc[2 * np],     qf[kk], b0, b1);
                mma16(sc[2 * np + 1], qf[kk], b2, b3);
            }
        }

#pragma unroll
        for (int nt = 0; nt < 8; nt++) {
            int col = kt * 64 + nt * 8 + 2 * tg;
            float mk0 = Msk[col], mk1 = Msk[col + 1];
            float e0 = __expf(sc[nt][0] * 0.125f + mk0);
            float e1 = __expf(sc[nt][1] * 0.125f + mk1);
            float e2 = __expf(sc[nt][2] * 0.125f + mk0);
            float e3 = __expf(sc[nt][3] * 0.125f + mk1);
            l_lo += e0 + e1;
            l_hi += e2 + e3;
            *(__half2*)(Psb + rm * 72 + nt * 8 + 2 * tg) =
                __floats2half2_rn(e0, e1);
            *(__half2*)(Psb + (rm + 8) * 72 + nt * 8 + 2 * tg) =
                __floats2half2_rn(e2, e3);
        }
        __syncwarp();

#pragma unroll
        for (int kk = 0; kk < 4; kk++) {
            uint32_t pa[4];
            ldm_x4(pa[0], pa[1], pa[2], pa[3],
                   sptr(Psb + prow * 72 + kk * 16 + pcol));
#pragma unroll
            for (int p = 0; p < 4; p++) {
                uint32_t b0, b1, b2, b3;
                int krow = kk * 16 + lmh * 8 + lr;
                int ncol = p * 16 + lkh * 8;
                ldm_x4t(b0, b1, b2, b3,
                        sptr(VsB + st * 4608 + krow * 72 + ncol));
                mma16(of[2 * p],     pa, b0, b1);
                mma16(of[2 * p + 1], pa, b2, b3);
            }
        }
    }
#undef LOAD_KV

    l_lo += __shfl_xor_sync(0xffffffffu, l_lo, 1);
    l_lo += __shfl_xor_sync(0xffffffffu, l_lo, 2);
    l_hi += __shfl_xor_sync(0xffffffffu, l_hi, 1);
    l_hi += __shfl_xor_sync(0xffffffffu, l_hi, 2);

    float inv_lo = 1.f / l_lo, inv_hi = 1.f / l_hi;
    size_t r_lo = brow + qt * 128 + rm;
    size_t r_hi = r_lo + 8;
#pragma unroll
    for (int nt = 0; nt < 8; nt++) {
        size_t col = hcol + nt * 8 + 2 * tg;
        *(__half2*)(O + r_lo * Dv + col) =
            __floats2half2_rn(of[nt][0] * inv_lo, of[nt][1] * inv_lo);
        *(__half2*)(O + r_hi * Dv + col) =
            __floats2half2_rn(of[nt][2] * inv_hi, of[nt][3] * inv_hi);
    }
}

// ---------------------------------------------------------------------------
// LayerNorm finalize (32 partials per batch) + apply (half residual input)
// ---------------------------------------------------------------------------
__global__ void ln_finalize32(const float* __restrict__ part,
                              float* __restrict__ stats)
{
    const int b = blockIdx.x;
    const int t = threadIdx.x;    // 32
    float s  = part[(b * 32 + t) * 2 + 0];
    float s2 = part[(b * 32 + t) * 2 + 1];
#pragma unroll
    for (int m = 16; m; m >>= 1) {
        s  += __shfl_xor_sync(0xffffffffu, s, m);
        s2 += __shfl_xor_sync(0xffffffffu, s2, m);
    }
    if (t == 0) {
        float n = (float)SDv;
        float mean = s / n;
        float var  = s2 / n - mean * mean;
        stats[b * 2 + 0] = mean;
        stats[b * 2 + 1] = rsqrtf(var + 1e-5f);
    }
}

template <int OUT_HALF>
__global__ void __launch_bounds__(256) ln_apply_h(
    const __half* __restrict__ Rh, const float* __restrict__ stats,
    const float* __restrict__ W, const float* __restrict__ Bb,
    float* __restrict__ out, __half* __restrict__ outh)
{
    size_t i4 = (size_t)blockIdx.x * 256 + threadIdx.x;
    size_t e  = i4 * 4;
    int b  = (int)(e >> 19);
    int sd = (int)(e & (SDv - 1));
    float mean = stats[b * 2 + 0];
    float rstd = stats[b * 2 + 1];
    __half2 ra = *(const __half2*)(Rh + e);
    __half2 rb = *(const __half2*)(Rh + e + 2);
    float4 w4 = *(const float4*)(W + sd);
    float4 b4 = *(const float4*)(Bb + sd);
    float y0 = (__low2float(ra)  - mean) * rstd * w4.x + b4.x;
    float y1 = (__high2float(ra) - mean) * rstd * w4.y + b4.y;
    float y2 = (__low2float(rb)  - mean) * rstd * w4.z + b4.z;
    float y3 = (__high2float(rb) - mean) * rstd * w4.w + b4.w;
    if (OUT_HALF) {
        *(__half2*)(outh + e)     = __floats2half2_rn(y0, y1);
        *(__half2*)(outh + e + 2) = __floats2half2_rn(y2, y3);
    } else {
        *(float4*)(out + e) = make_float4(y0, y1, y2, y3);
    }
}

// ---------------------------------------------------------------------------
extern "C" void kernel_launch(void* const* d_in, const int* in_sizes, int n_in,
                              void* d_out, int out_size)
{
    const float* x    = (const float*)d_in[0];
    const float* mask = (const float*)d_in[1];
    const float* wq   = (const float*)d_in[2];
    const float* bq   = (const float*)d_in[3];
    const float* wk   = (const float*)d_in[4];
    const float* bk   = (const float*)d_in[5];
    const float* wv   = (const float*)d_in[6];
    const float* bv   = (const float*)d_in[7];
    const float* wo   = (const float*)d_in[8];
    const float* bo   = (const float*)d_in[9];
    const float* w1   = (const float*)d_in[10];
    const float* b1   = (const float*)d_in[11];
    const float* w2   = (const float*)d_in[12];
    const float* b2   = (const float*)d_in[13];
    const float* ln1w = (const float*)d_in[14];
    const float* ln1b = (const float*)d_in[15];
    const float* ln2w = (const float*)d_in[16];
    const float* ln2b = (const float*)d_in[17];
    float* out = (float*)d_out;

    void* p;
    cudaGetSymbolAddress(&p, g_xh);      __half* xh    = (__half*)p;
    cudaGetSymbolAddress(&p, g_qkvh);    __half* qkvh  = (__half*)p;
    cudaGetSymbolAddress(&p, g_ctxh);    __half* ctxh  = (__half*)p;
    cudaGetSymbolAddress(&p, g_o1h);     __half* o1h   = (__half*)p;
    cudaGetSymbolAddress(&p, g_ffnh);    __half* ffnh  = (__half*)p;
    cudaGetSymbolAddress(&p, g_res1h);   __half* res1h = (__half*)p;
    cudaGetSymbolAddress(&p, g_res2h);   __half* res2h = (__half*)p;
    cudaGetSymbolAddress(&p, g_wqkvh);   __half* wqkvh = (__half*)p;
    cudaGetSymbolAddress(&p, g_woh);     __half* woh   = (__half*)p;
    cudaGetSymbolAddress(&p, g_w1h);     __half* w1h   = (__half*)p;
    cudaGetSymbolAddress(&p, g_w2h);     __half* w2h   = (__half*)p;
    cudaGetSymbolAddress(&p, g_bqkv);    float* bqkv   = (float*)p;
    cudaGetSymbolAddress(&p, g_part1);   float* part1  = (float*)p;
    cudaGetSymbolAddress(&p, g_part2);   float* part2  = (float*)p;
    cudaGetSymbolAddress(&p, g_stats1);  float* stats1 = (float*)p;
    cudaGetSymbolAddress(&p, g_stats2);  float* stats2 = (float*)p;

    cudaFuncSetAttribute(attn_h,
                         cudaFuncAttributeMaxDynamicSharedMemorySize, ATT_SMEM);
    cudaFuncSetAttribute(gemm_h<0, 0, 0>,
                         cudaFuncAttributeMaxDynamicSharedMemorySize, GEMM_SMEM);
    cudaFuncSetAttribute(gemm_h<0, 1, 0>,
                         cudaFuncAttributeMaxDynamicSharedMemorySize, GEMM_SMEM);
    cudaFuncSetAttribute(gemm_h<1, 0, 0>,
                         cudaFuncAttributeMaxDynamicSharedMemorySize, GEMM_SMEM);
    cudaFuncSetAttribute(gemm_h<0, 1, 1>,
                         cudaFuncAttributeMaxDynamicSharedMemorySize, GEMM_SMEM);

    dim3 blk(256);
    dim3 gQKV(QS / 128, BSv / 128);    // (12, 128)
    dim3 gD(Dv / 128, BSv / 128);      // (4, 128)
    dim3 gF(DFFv / 128, BSv / 128);    // (16, 128)
    dim3 gAttn(Sv / 128, Bv * 8);      // (8, 128)
    int  gApply = (BSv * Dv / 4) / 256;

    prep<<<11265, 256>>>(x, wq, wk, wv, wo, w1, w2, bq, bk, bv,
                         xh, wqkvh, woh, w1h, w2h, bqkv);

    // fused QKV projection (half out, packed)
    gemm_h<0, 0, 0><<<gQKV, blk, GEMM_SMEM>>>(xh, wqkvh, bqkv, qkvh,
                                              nullptr, nullptr, nullptr, QS, Dv);

    // attention
    attn_h<<<gAttn, blk, ATT_SMEM>>>(qkvh, mask, ctxh);

    // O-projection fused with fp32-x residual + LN1 partials; res1 stored half
    gemm_h<0, 1, 0><<<gD, blk, GEMM_SMEM>>>(ctxh, woh, bo, res1h,
                                            x, nullptr, part1, Dv, Dv);
    ln_finalize32<<<Bv, 32>>>(part1, stats1);
    ln_apply_h<1><<<gApply, blk>>>(res1h, stats1, ln1w, ln1b, nullptr, o1h);

    // FFN1 (half out)
    gemm_h<1, 0, 0><<<gF, blk, GEMM_SMEM>>>(o1h, w1h, b1, ffnh,
                                            nullptr, nullptr, nullptr, DFFv, Dv);
    // FFN2 fused with half-o1h residual + LN2 partials; res2 stored half
    gemm_h<0, 1, 1><<<gD, blk, GEMM_SMEM>>>(ffnh, w2h, b2, res2h,
                                            nullptr, o1h, part2, Dv, DFFv);
    ln_finalize32<<<Bv, 32>>>(part2, stats2);
    ln_apply_h<0><<<gApply, blk>>>(res2h, stats2, ln2w, ln2b, out, nullptr);
}

// round 16
// speedup vs baseline: 1.1355x; 1.0033x over previous
#include <cuda_runtime.h>
#include <cuda_fp16.h>
#include <cstdint>
#include <math.h>

// Problem constants
static const int Bv   = 16;
static const int Sv   = 1024;
static const int Dv   = 512;
static const int DFFv = 2048;
static const int BSv  = Bv * Sv;        // 16384
static const int SDv  = Sv * Dv;        // 524288 = 2^19
static const int QS   = 1536;           // packed QKV row stride

// ---------------- scratch (device globals; no allocation allowed) ----------
__device__ __half g_xh[BSv * Dv];
__device__ __half g_qkvh[BSv * QS];       // packed q|k|v, row stride 1536
__device__ __half g_ctxh[BSv * Dv];
__device__ __half g_o1h[BSv * Dv];
__device__ __half g_ffnh[BSv * DFFv];
__device__ __half g_res1h[BSv * Dv];
__device__ __half g_res2h[BSv * Dv];
__device__ __half g_wqkvh[Dv * QS];       // packed weights [K=512][N=1536]
__device__ __half g_woh[Dv * Dv];
__device__ __half g_w1h[Dv * DFFv];
__device__ __half g_w2h[DFFv * Dv];
__device__ float g_bqkv[QS];              // packed bias
__device__ float g_part1[512 * 2];
__device__ float g_part2[512 * 2];

// ---------------------------------------------------------------------------
// helpers
// ---------------------------------------------------------------------------
__device__ __forceinline__ void cp16(uint32_t dst, const void* src) {
    asm volatile("cp.async.cg.shared.global [%0], [%1], 16;"
                 :: "r"(dst), "l"(src));
}
__device__ __forceinline__ void cp_commit() {
    asm volatile("cp.async.commit_group;");
}
__device__ __forceinline__ void ldm_x4(uint32_t& r0, uint32_t& r1,
                                       uint32_t& r2, uint32_t& r3, uint32_t a) {
    asm volatile("ldmatrix.sync.aligned.m8n8.x4.shared.b16 {%0,%1,%2,%3}, [%4];"
                 : "=r"(r0), "=r"(r1), "=r"(r2), "=r"(r3) : "r"(a));
}
__device__ __forceinline__ void ldm_x4t(uint32_t& r0, uint32_t& r1,
                                        uint32_t& r2, uint32_t& r3, uint32_t a) {
    asm volatile("ldmatrix.sync.aligned.m8n8.x4.trans.shared.b16 {%0,%1,%2,%3}, [%4];"
                 : "=r"(r0), "=r"(r1), "=r"(r2), "=r"(r3) : "r"(a));
}
__device__ __forceinline__ void mma16(float* d, const uint32_t* a,
                                      uint32_t b0, uint32_t b1) {
    asm volatile(
        "mma.sync.aligned.m16n8k16.row.col.f32.f16.f16.f32 "
        "{%0,%1,%2,%3}, {%4,%5,%6,%7}, {%8,%9}, {%0,%1,%2,%3};"
        : "+f"(d[0]), "+f"(d[1]), "+f"(d[2]), "+f"(d[3])
        : "r"(a[0]), "r"(a[1]), "r"(a[2]), "r"(a[3]), "r"(b0), "r"(b1));
}
__device__ __forceinline__ uint32_t sptr(const void* p) {
    return (uint32_t)__cvta_generic_to_shared(p);
}

// ---------------------------------------------------------------------------
// fp16 tensor-core GEMM: round-9/14/15 proven config. CTA 128x128, BK=32, 256
// threads (8 warps 4x2, warp tile 32x64), 3-stage cp.async pipeline, one
// barrier per iteration, B-fragment software pipelining.
// FUSE: epilogue adds residual (fp32 Xres or half Xresh per XHALF), LN
// partials computed from exact fp32 values, result stored HALF.
// ---------------------------------------------------------------------------
#define ASTG (128 * 40)            // halfs per A stage
#define BSTG (32 * 136)            // halfs per B stage
#define STG  (ASTG + BSTG)         // 9472 halfs = 18944 B
#define GEMM_SMEM (3 * STG * 2)    // 56832 B

template <int RELU, int FUSE, int XHALF>
__global__ void __launch_bounds__(256, 2) gemm_h(
    const __half* __restrict__ A, const __half* __restrict__ Bw,
    const float* __restrict__ bias, __half* __restrict__ Ch,
    const float* __restrict__ Xres, const __half* __restrict__ Xresh,
    float* __restrict__ part, int N, int K)
{
    extern __shared__ __align__(16) __half smh[];

    const int tid = threadIdx.x;
    const int lane = tid & 31, wid = tid >> 5;
    const int qid = lane >> 2, tg = lane & 3;
    const int wm = (wid & 3) * 32, wn = (wid >> 2) * 64;
    const int m0 = blockIdx.y * 128, n0 = blockIdx.x * 128;

    float acc[2][8][4];
#pragma unroll
    for (int mt = 0; mt < 2; mt++)
#pragma unroll
        for (int nt = 0; nt < 8; nt++)
#pragma unroll
            for (int r = 0; r < 4; r++) acc[mt][nt][r] = 0.f;

    const int lr = lane & 7;
    const int lmh = (lane >> 3) & 1;
    const int lkh = lane >> 4;

    const int a_row0 = tid >> 2,  a_seg = (tid & 3) * 8;
    const int b_row0 = tid >> 4,  b_seg = (tid & 15) * 8;

#define LOAD_STAGE(st, k0)                                                     \
    {                                                                          \
        __half* As_ = smh + (st) * STG;                                        \
        __half* Bs_ = smh + (st) * STG + ASTG;                                 \
        cp16(sptr(As_ + a_row0 * 40 + a_seg),                                  \
             A + (size_t)(m0 + a_row0) * K + (k0) + a_seg);                    \
        cp16(sptr(As_ + (a_row0 + 64) * 40 + a_seg),                           \
             A + (size_t)(m0 + a_row0 + 64) * K + (k0) + a_seg);               \
        cp16(sptr(Bs_ + b_row0 * 136 + b_seg),                                 \
             Bw + (size_t)((k0) + b_row0) * N + n0 + b_seg);                   \
        cp16(sptr(Bs_ + (b_row0 + 16) * 136 + b_seg),                          \
             Bw + (size_t)((k0) + b_row0 + 16) * N + n0 + b_seg);              \
    }

    const int nk = K >> 5;
    LOAD_STAGE(0, 0);  cp_commit();
    LOAD_STAGE(1, 32); cp_commit();

    for (int it = 0; it < nk; it++) {
        const int st = it % 3;
        asm volatile("cp.async.wait_group 1;");
        __syncthreads();

        if (it + 2 < nk) {
            LOAD_STAGE((it + 2) % 3, (it + 2) * 32);
            cp_commit();
        } else {
            cp_commit();
        }

        const __half* As_ = smh + st * STG;
        const __half* Bs_ = smh + st * STG + ASTG;

#pragma unroll
        for (int ko2 = 0; ko2 < 2; ko2++) {
            const int ko = ko2 * 16;
            uint32_t af[2][4];
#pragma unroll
            for (int mt = 0; mt < 2; mt++) {
                int mrow = wm + mt * 16 + lmh * 8 + lr;
                ldm_x4(af[mt][0], af[mt][1], af[mt][2], af[mt][3],
                       sptr(As_ + mrow * 40 + ko + lkh * 8));
            }
            const int krow = ko + lmh * 8 + lr;
            uint32_t bf[2][4];
            ldm_x4t(bf[0][0], bf[0][1], bf[0][2], bf[0][3],
                    sptr(Bs_ + krow * 136 + wn + lkh * 8));
#pragma unroll
            for (int p = 0; p < 4; p++) {
                const int cur = p & 1, nxt = cur ^ 1;
                if (p < 3)
                    ldm_x4t(bf[nxt][0], bf[nxt][1], bf[nxt][2], bf[nxt][3],
                            sptr(Bs_ + krow * 136 + wn + (p + 1) * 16 + lkh * 8));
                mma16(acc[0][2 * p],     af[0], bf[cur][0], bf[cur][1]);
                mma16(acc[1][2 * p],     af[1], bf[cur][0], bf[cur][1]);
                mma16(acc[0][2 * p + 1], af[0], bf[cur][2], bf[cur][3]);
                mma16(acc[1][2 * p + 1], af[1], bf[cur][2], bf[cur][3]);
            }
        }
    }
#undef LOAD_STAGE

    float s = 0.f, s2 = 0.f;
#pragma unroll
    for (int mt = 0; mt < 2; mt++) {
        int r_lo = m0 + wm + mt * 16 + qid;
        int r_hi = r_lo + 8;
#pragma unroll
        for (int nt = 0; nt < 8; nt++) {
            int col = n0 + wn + nt * 8 + 2 * tg;
            float bx = bias[col], by = bias[col + 1];
            float v0 = acc[mt][nt][0] + bx, v1 = acc[mt][nt][1] + by;
            float v2 = acc[mt][nt][2] + bx, v3 = acc[mt][nt][3] + by;
            if (RELU) {
                v0 = fmaxf(v0, 0.f); v1 = fmaxf(v1, 0.f);
                v2 = fmaxf(v2, 0.f); v3 = fmaxf(v3, 0.f);
            }
            if (FUSE) {
                if (XHALF) {
                    __half2 xa = *(const __half2*)(Xresh + (size_t)r_lo * N + col);
                    __half2 xb = *(const __half2*)(Xresh + (size_t)r_hi * N + col);
                    v0 += __low2float(xa);  v1 += __high2float(xa);
                    v2 += __low2float(xb);  v3 += __high2float(xb);
                } else {
                    float2 xa = *(const float2*)(Xres + (size_t)r_lo * N + col);
                    float2 xb = *(const float2*)(Xres + (size_t)r_hi * N + col);
                    v0 += xa.x; v1 += xa.y; v2 += xb.x; v3 += xb.y;
                }
                s  += v0 + v1 + v2 + v3;
                s2 += v0 * v0 + v1 * v1 + v2 * v2 + v3 * v3;
            }
            *(__half2*)(Ch + (size_t)r_lo * N + col) = __floats2half2_rn(v0, v1);
            *(__half2*)(Ch + (size_t)r_hi * N + col) = __floats2half2_rn(v2, v3);
        }
    }

    if (FUSE) {
        float* rsum  = (float*)smh;
        float* rsum2 = rsum + 256;
        __syncthreads();
        rsum[tid] = s; rsum2[tid] = s2;
        __syncthreads();
        for (int off = 128; off > 0; off >>= 1) {
            if (tid < off) { rsum[tid] += rsum[tid + off]; rsum2[tid] += rsum2[tid + off]; }
            __syncthreads();
        }
        if (tid == 0) {
            int pidx = blockIdx.y * gridDim.x + blockIdx.x;
            part[2 * pidx]     = rsum[0];
            part[2 * pidx + 1] = rsum2[0];
        }
    }
}

// ---------------------------------------------------------------------------
// Single prep kernel
// ---------------------------------------------------------------------------
__global__ void __launch_bounds__(256) prep(
    const float* __restrict__ x,
    const float* __restrict__ wq, const float* __restrict__ wk,
    const float* __restrict__ wv, const float* __restrict__ wo,
    const float* __restrict__ w1, const float* __restrict__ w2,
    const float* __restrict__ bq, const float* __restrict__ bk,
    const float* __restrict__ bv,
    __half* __restrict__ xh, __half* __restrict__ wqkvh,
    __half* __restrict__ woh, __half* __restrict__ w1h,
    __half* __restrict__ w2h, float* __restrict__ bqkv)
{
    const int blk = blockIdx.x;
    const int tid = threadIdx.x;

    if (blk < 10496) {
        const float* src; __half* dst; size_t base;
        if (blk < 8192)       { src = x;  dst = xh;  base = (size_t)blk * 1024; }
        else if (blk < 8448)  { src = wo; dst = woh; base = (size_t)(blk - 8192) * 1024; }
        else if (blk < 9472)  { src = w1; dst = w1h; base = (size_t)(blk - 8448) * 1024; }
        else                  { src = w2; dst = w2h; base = (size_t)(blk - 9472) * 1024; }
        size_t i = base + (size_t)tid * 4;
        float4 v = *(const float4*)(src + i);
        *(__half2*)(dst + i)     = __floats2half2_rn(v.x, v.y);
        *(__half2*)(dst + i + 2) = __floats2half2_rn(v.z, v.w);
    } else if (blk < 11264) {
        const float* src; int off; int sb;
        if (blk < 10752)      { src = wq; off = 0;    sb = blk - 10496; }
        else if (blk < 11008) { src = wk; off = 512;  sb = blk - 10752; }
        else                  { src = wv; off = 1024; sb = blk - 11008; }
        size_t i = (size_t)sb * 1024 + (size_t)tid * 4;
        int row = (int)(i >> 9), col = (int)(i & 511);
        float4 v = *(const float4*)(src + i);
        __half* d = wqkvh + (size_t)row * QS + off + col;
        *(__half2*)(d)     = __floats2half2_rn(v.x, v.y);
        *(__half2*)(d + 2) = __floats2half2_rn(v.z, v.w);
    } else {
        for (int i = tid; i < 1536; i += 256)
            bqkv[i] = (i < 512) ? bq[i] : (i < 1024) ? bk[i - 512] : bv[i - 1024];
    }
}

// ---------------------------------------------------------------------------
// Flash attention, fp16 MMAs. grid = (S/128, B*H), block = 256 (8 warps).
// Fixed m=0 softmax; l reduced once at the end; all K/P fragments via
// ldmatrix.x4. (round-14/15 best, unchanged)
// ---------------------------------------------------------------------------
#define ATT_SMEM 59392

__global__ void __launch_bounds__(256) attn_h(
    const __half* __restrict__ QKV, const float* __restrict__ mask,
    __half* __restrict__ O)
{
    extern __shared__ __align__(16) char smraw[];
    __half* KsB = (__half*)smraw;                  // [2][64][72]
    __half* VsB = (__half*)(smraw + 18432);        // [2][64][72]
    __half* Psb = (__half*)(smraw + 36864);        // [128][72]
    float*  Msk = (float*)(smraw + 55296);         // [1024]

    const int tid = threadIdx.x;
    const int lane = tid & 31, wid = tid >> 5;
    const int qid = lane >> 2, tg = lane & 3;
    const int lr = lane & 7, lg = lane >> 3;
    const int lmh = lg & 1, lkh = lane >> 4;
    const int qt = blockIdx.x;
    const int b  = blockIdx.y >> 3;
    const int h  = blockIdx.y & 7;
    const size_t hcol = (size_t)h * 64;
    const size_t brow = (size_t)b * Sv;

#define LOAD_KV(st, kt)                                                        \
    {                                                                          \
        _Pragma("unroll")                                                      \
        for (int i = 0; i < 2; i++) {                                          \
            int c = tid + i * 256;                                             \
            int row = c >> 3, seg = c & 7;                                     \
            size_t g = (brow + (kt) * 64 + row) * QS + hcol + seg * 8;         \
            cp16(sptr(KsB + (st) * 4608 + row * 72 + seg * 8), QKV + g + 512); \
            cp16(sptr(VsB + (st) * 4608 + row * 72 + seg * 8), QKV + g + 1024);\
        }                                                                      \
    }

    LOAD_KV(0, 0);
    cp_commit();

#pragma unroll
    for (int i = 0; i < 4; i++)
        Msk[tid + i * 256] = mask[b * Sv + tid + i * 256] * -1e9f;

#pragma unroll
    for (int i = 0; i < 4; i++) {
        int c = tid + i * 256;
        int row = c >> 3, seg = c & 7;
        *(uint4*)(Psb + row * 72 + seg * 8) =
            *(const uint4*)(QKV + (brow + qt * 128 + row) * QS + hcol + seg * 8);
    }
    __syncthreads();

    const int rm = wid * 16 + qid;
    uint32_t qf[4][4];
    {
        const int qrow = wid * 16 + (lg & 1) * 8 + lr;
        const int qcol = (lg >> 1) * 8;
#pragma unroll
        for (int kk = 0; kk < 4; kk++)
            ldm_x4(qf[kk][0], qf[kk][1], qf[kk][2], qf[kk][3],
                   sptr(Psb + qrow * 72 + kk * 16 + qcol));
    }

    float l_lo = 0.f, l_hi = 0.f;
    float of[8][4];
#pragma unroll
    for (int nt = 0; nt < 8; nt++)
#pragma unroll
        for (int r = 0; r < 4; r++) of[nt][r] = 0.f;

    const int krow_off = (lg >> 1) * 8 + lr;
    const int kcol_off = (lg & 1) * 8;
    const int prow = wid * 16 + (lg & 1) * 8 + lr;
    const int pcol = (lg >> 1) * 8;

    for (int kt = 0; kt < 16; kt++) {
        const int st = kt & 1;
        asm volatile("cp.async.wait_group 0;");
        __syncthreads();
        if (kt + 1 < 16) {
            LOAD_KV(st ^ 1, kt + 1);
            cp_commit();
        }

        float sc[8][4];
#pragma unroll
        for (int nt = 0; nt < 8; nt++)
#pragma unroll
            for (int r = 0; r < 4; r++) sc[nt][r] = 0.f;

        const __half* Kb = KsB + st * 4608;
#pragma unroll
        for (int kk = 0; kk < 4; kk++) {
#pragma unroll
            for (int np = 0; np < 4; np++) {
                uint32_t b0, b1, b2, b3;
                ldm_x4(b0, b1, b2, b3,
                       sptr(Kb + (np * 16 + krow_off) * 72 + kk * 16 + kcol_off));
                mma16(sc[2 * np],     qf[kk], b0, b1);
                mma16(sc[2 * np + 1], qf[kk], b2, b3);
            }
        }

#pragma unroll
        for (int nt = 0; nt < 8; nt++) {
            int col = kt * 64 + nt * 8 + 2 * tg;
            float mk0 = Msk[col], mk1 = Msk[col + 1];
            float e0 = __expf(sc[nt][0] * 0.125f + mk0);
            float e1 = __expf(sc[nt][1] * 0.125f + mk1);
            float e2 = __expf(sc[nt][2] * 0.125f + mk0);
            float e3 = __expf(sc[nt][3] * 0.125f + mk1);
            l_lo += e0 + e1;
            l_hi += e2 + e3;
            *(__half2*)(Psb + rm * 72 + nt * 8 + 2 * tg) =
                __floats2half2_rn(e0, e1);
            *(__half2*)(Psb + (rm + 8) * 72 + nt * 8 + 2 * tg) =
                __floats2half2_rn(e2, e3);
        }
        __syncwarp();

#pragma unroll
        for (int kk = 0; kk < 4; kk++) {
            uint32_t pa[4];
            ldm_x4(pa[0], pa[1], pa[2], pa[3],
                   sptr(Psb + prow * 72 + kk * 16 + pcol));
#pragma unroll
            for (int p = 0; p < 4; p++) {
                uint32_t b0, b1, b2, b3;
                int krow = kk * 16 + lmh * 8 + lr;
                int ncol = p * 16 + lkh * 8;
                ldm_x4t(b0, b1, b2, b3,
                        sptr(VsB + st * 4608 + krow * 72 + ncol));
                mma16(of[2 * p],     pa, b0, b1);
                mma16(of[2 * p + 1], pa, b2, b3);
            }
        }
    }
#undef LOAD_KV

    l_lo += __shfl_xor_sync(0xffffffffu, l_lo, 1);
    l_lo += __shfl_xor_sync(0xffffffffu, l_lo, 2);
    l_hi += __shfl_xor_sync(0xffffffffu, l_hi, 1);
    l_hi += __shfl_xor_sync(0xffffffffu, l_hi, 2);

    float inv_lo = 1.f / l_lo, inv_hi = 1.f / l_hi;
    size_t r_lo = brow + qt * 128 + rm;
    size_t r_hi = r_lo + 8;
#pragma unroll
    for (int nt = 0; nt < 8; nt++) {
        size_t col = hcol + nt * 8 + 2 * tg;
        *(__half2*)(O + r_lo * Dv + col) =
            __floats2half2_rn(of[nt][0] * inv_lo, of[nt][1] * inv_lo);
        *(__half2*)(O + r_hi * Dv + col) =
            __floats2half2_rn(of[nt][2] * inv_hi, of[nt][3] * inv_hi);
    }
}

// ---------------------------------------------------------------------------
// Fused LN finalize+apply: each block re-reduces the batch's 32 partials
// (cheap, L2-resident) and applies LN to its 2048-element slice.
// grid = 4096 blocks (128 elems/thread-group slice => 8 elems/thread),
// block = 256. OUT_HALF selects fp32 out vs half out.
// ---------------------------------------------------------------------------
template <int OUT_HALF>
__global__ void __launch_bounds__(256) ln_apply_f(
    const __half* __restrict__ Rh, const float* __restrict__ part,
    const float* __restrict__ W, const float* __restrict__ Bb,
    float* __restrict__ out, __half* __restrict__ outh)
{
    // each block: 256 threads x 8 elements = 2048 elements
    const size_t base = (size_t)blockIdx.x * 2048;
    const int b = (int)(base >> 19);

    __shared__ float sh_mean, sh_rstd;
    if (threadIdx.x < 32) {
        float s  = part[(b * 32 + threadIdx.x) * 2 + 0];
        float s2 = part[(b * 32 + threadIdx.x) * 2 + 1];
#pragma unroll
        for (int m = 16; m; m >>= 1) {
            s  += __shfl_xor_sync(0xffffffffu, s, m);
            s2 += __shfl_xor_sync(0xffffffffu, s2, m);
        }
        if (threadIdx.x == 0) {
            float n = (float)SDv;
            float mean = s / n;
            float var  = s2 / n - mean * mean;
            sh_mean = mean;
            sh_rstd = rsqrtf(var + 1e-5f);
        }
    }
    __syncthreads();
    const float mean = sh_mean, rstd = sh_rstd;

#pragma unroll
    for (int j = 0; j < 2; j++) {
        size_t e  = base + (size_t)(threadIdx.x + j * 256) * 4;
        int sd = (int)(e & (SDv - 1));
        __half2 ra = *(const __half2*)(Rh + e);
        __half2 rb = *(const __half2*)(Rh + e + 2);
        float4 w4 = *(const float4*)(W + sd);
        float4 b4 = *(const float4*)(Bb + sd);
        float y0 = (__low2float(ra)  - mean) * rstd * w4.x + b4.x;
        float y1 = (__high2float(ra) - mean) * rstd * w4.y + b4.y;
        float y2 = (__low2float(rb)  - mean) * rstd * w4.z + b4.z;
        float y3 = (__high2float(rb) - mean) * rstd * w4.w + b4.w;
        if (OUT_HALF) {
            *(__half2*)(outh + e)     = __floats2half2_rn(y0, y1);
            *(__half2*)(outh + e + 2) = __floats2half2_rn(y2, y3);
        } else {
            *(float4*)(out + e) = make_float4(y0, y1, y2, y3);
        }
    }
}

// ---------------------------------------------------------------------------
extern "C" void kernel_launch(void* const* d_in, const int* in_sizes, int n_in,
                              void* d_out, int out_size)
{
    const float* x    = (const float*)d_in[0];
    const float* mask = (const float*)d_in[1];
    const float* wq   = (const float*)d_in[2];
    const float* bq   = (const float*)d_in[3];
    const float* wk   = (const float*)d_in[4];
    const float* bk   = (const float*)d_in[5];
    const float* wv   = (const float*)d_in[6];
    const float* bv   = (const float*)d_in[7];
    const float* wo   = (const float*)d_in[8];
    const float* bo   = (const float*)d_in[9];
    const float* w1   = (const float*)d_in[10];
    const float* b1   = (const float*)d_in[11];
    const float* w2   = (const float*)d_in[12];
    const float* b2   = (const float*)d_in[13];
    const float* ln1w = (const float*)d_in[14];
    const float* ln1b = (const float*)d_in[15];
    const float* ln2w = (const float*)d_in[16];
    const float* ln2b = (const float*)d_in[17];
    float* out = (float*)d_out;

    void* p;
    cudaGetSymbolAddress(&p, g_xh);      __half* xh    = (__half*)p;
    cudaGetSymbolAddress(&p, g_qkvh);    __half* qkvh  = (__half*)p;
    cudaGetSymbolAddress(&p, g_ctxh);    __half* ctxh  = (__half*)p;
    cudaGetSymbolAddress(&p, g_o1h);     __half* o1h   = (__half*)p;
    cudaGetSymbolAddress(&p, g_ffnh);    __half* ffnh  = (__half*)p;
    cudaGetSymbolAddress(&p, g_res1h);   __half* res1h = (__half*)p;
    cudaGetSymbolAddress(&p, g_res2h);   __half* res2h = (__half*)p;
    cudaGetSymbolAddress(&p, g_wqkvh);   __half* wqkvh = (__half*)p;
    cudaGetSymbolAddress(&p, g_woh);     __half* woh   = (__half*)p;
    cudaGetSymbolAddress(&p, g_w1h);     __half* w1h   = (__half*)p;
    cudaGetSymbolAddress(&p, g_w2h);     __half* w2h   = (__half*)p;
    cudaGetSymbolAddress(&p, g_bqkv);    float* bqkv   = (float*)p;
    cudaGetSymbolAddress(&p, g_part1);   float* part1  = (float*)p;
    cudaGetSymbolAddress(&p, g_part2);   float* part2  = (float*)p;

    cudaFuncSetAttribute(attn_h,
                         cudaFuncAttributeMaxDynamicSharedMemorySize, ATT_SMEM);
    cudaFuncSetAttribute(gemm_h<0, 0, 0>,
                         cudaFuncAttributeMaxDynamicSharedMemorySize, GEMM_SMEM);
    cudaFuncSetAttribute(gemm_h<0, 1, 0>,
                         cudaFuncAttributeMaxDynamicSharedMemorySize, GEMM_SMEM);
    cudaFuncSetAttribute(gemm_h<1, 0, 0>,
                         cudaFuncAttributeMaxDynamicSharedMemorySize, GEMM_SMEM);
    cudaFuncSetAttribute(gemm_h<0, 1, 1>,
                         cudaFuncAttributeMaxDynamicSharedMemorySize, GEMM_SMEM);

    dim3 blk(256);
    dim3 gQKV(QS / 128, BSv / 128);    // (12, 128)
    dim3 gD(Dv / 128, BSv / 128);      // (4, 128)
    dim3 gF(DFFv / 128, BSv / 128);    // (16, 128)
    dim3 gAttn(Sv / 128, Bv * 8);      // (8, 128)
    int  gApply = (BSv * Dv) / 2048;   // 4096

    prep<<<11265, 256>>>(x, wq, wk, wv, wo, w1, w2, bq, bk, bv,
                         xh, wqkvh, woh, w1h, w2h, bqkv);

    // fused QKV projection (half out, packed)
    gemm_h<0, 0, 0><<<gQKV, blk, GEMM_SMEM>>>(xh, wqkvh, bqkv, qkvh,
                                              nullptr, nullptr, nullptr, QS, Dv);

    // attention
    attn_h<<<gAttn, blk, ATT_SMEM>>>(qkvh, mask, ctxh);

    // O-projection fused with fp32-x residual + LN1 partials; res1 stored half
    gemm_h<0, 1, 0><<<gD, blk, GEMM_SMEM>>>(ctxh, woh, bo, res1h,
                                            x, nullptr, part1, Dv, Dv);
    ln_apply_f<1><<<gApply, blk>>>(res1h, part1, ln1w, ln1b, nullptr, o1h);

    // FFN1 (half out)
    gemm_h<1, 0, 0><<<gF, blk, GEMM_SMEM>>>(o1h, w1h, b1, ffnh,
                                            nullptr, nullptr, nullptr, DFFv, Dv);
    // FFN2 fused with half-o1h residual + LN2 partials; res2 stored half
    gemm_h<0, 1, 1><<<gD, blk, GEMM_SMEM>>>(ffnh, w2h, b2, res2h,
                                            nullptr, o1h, part2, Dv, DFFv);
    ln_apply_f<0><<<gApply, blk>>>(res2h, part2, ln2w, ln2b, out, nullptr);
}

// round 17
// speedup vs baseline: 1.1381x; 1.0023x over previous
#include <cuda_runtime.h>
#include <cuda_fp16.h>
#include <cstdint>
#include <math.h>

// Problem constants
static const int Bv   = 16;
static const int Sv   = 1024;
static const int Dv   = 512;
static const int DFFv = 2048;
static const int BSv  = Bv * Sv;        // 16384
static const int SDv  = Sv * Dv;        // 524288 = 2^19
static const int QS   = 1536;           // packed QKV row stride

// ---------------- scratch (device globals; no allocation allowed) ----------
__device__ __half g_xh[BSv * Dv];
__device__ __half g_qkvh[BSv * QS];       // packed q|k|v, row stride 1536
__device__ __half g_ctxh[BSv * Dv];
__device__ __half g_o1h[BSv * Dv];
__device__ __half g_ffnh[BSv * DFFv];
__device__ __half g_res1h[BSv * Dv];
__device__ __half g_res2h[BSv * Dv];
__device__ __half g_wqkvh[Dv * QS];       // packed weights [K=512][N=1536]
__device__ __half g_woh[Dv * Dv];
__device__ __half g_w1h[Dv * DFFv];
__device__ __half g_w2h[DFFv * Dv];
__device__ float g_bqkv[QS];              // packed bias
__device__ float g_part1[512 * 2];
__device__ float g_part2[512 * 2];

// ---------------------------------------------------------------------------
// helpers
// ---------------------------------------------------------------------------
__device__ __forceinline__ void cp16(uint32_t dst, const void* src) {
    asm volatile("cp.async.cg.shared.global [%0], [%1], 16;"
                 :: "r"(dst), "l"(src));
}
__device__ __forceinline__ void cp_commit() {
    asm volatile("cp.async.commit_group;");
}
__device__ __forceinline__ void ldm_x4(uint32_t& r0, uint32_t& r1,
                                       uint32_t& r2, uint32_t& r3, uint32_t a) {
    asm volatile("ldmatrix.sync.aligned.m8n8.x4.shared.b16 {%0,%1,%2,%3}, [%4];"
                 : "=r"(r0), "=r"(r1), "=r"(r2), "=r"(r3) : "r"(a));
}
__device__ __forceinline__ void ldm_x4t(uint32_t& r0, uint32_t& r1,
                                        uint32_t& r2, uint32_t& r3, uint32_t a) {
    asm volatile("ldmatrix.sync.aligned.m8n8.x4.trans.shared.b16 {%0,%1,%2,%3}, [%4];"
                 : "=r"(r0), "=r"(r1), "=r"(r2), "=r"(r3) : "r"(a));
}
__device__ __forceinline__ void mma16(float* d, const uint32_t* a,
                                      uint32_t b0, uint32_t b1) {
    asm volatile(
        "mma.sync.aligned.m16n8k16.row.col.f32.f16.f16.f32 "
        "{%0,%1,%2,%3}, {%4,%5,%6,%7}, {%8,%9}, {%0,%1,%2,%3};"
        : "+f"(d[0]), "+f"(d[1]), "+f"(d[2]), "+f"(d[3])
        : "r"(a[0]), "r"(a[1]), "r"(a[2]), "r"(a[3]), "r"(b0), "r"(b1));
}
__device__ __forceinline__ uint32_t sptr(const void* p) {
    return (uint32_t)__cvta_generic_to_shared(p);
}

// ---------------------------------------------------------------------------
// fp16 tensor-core GEMM: proven config. CTA 128x128, BK=32, 256 threads
// (8 warps 4x2, warp tile 32x64), 3-stage cp.async pipeline, one barrier per
// iteration, B-fragment software pipelining.
// FUSE: epilogue adds residual (fp32 Xres or half Xresh per XHALF), LN
// partials computed from exact fp32 values, result stored HALF.
// ---------------------------------------------------------------------------
#define ASTG (128 * 40)            // halfs per A stage
#define BSTG (32 * 136)            // halfs per B stage
#define STG  (ASTG + BSTG)         // 9472 halfs = 18944 B
#define GEMM_SMEM (3 * STG * 2)    // 56832 B

template <int RELU, int FUSE, int XHALF>
__global__ void __launch_bounds__(256, 2) gemm_h(
    const __half* __restrict__ A, const __half* __restrict__ Bw,
    const float* __restrict__ bias, __half* __restrict__ Ch,
    const float* __restrict__ Xres, const __half* __restrict__ Xresh,
    float* __restrict__ part, int N, int K)
{
    extern __shared__ __align__(16) __half smh[];

    const int tid = threadIdx.x;
    const int lane = tid & 31, wid = tid >> 5;
    const int qid = lane >> 2, tg = lane & 3;
    const int wm = (wid & 3) * 32, wn = (wid >> 2) * 64;
    const int m0 = blockIdx.y * 128, n0 = blockIdx.x * 128;

    float acc[2][8][4];
#pragma unroll
    for (int mt = 0; mt < 2; mt++)
#pragma unroll
        for (int nt = 0; nt < 8; nt++)
#pragma unroll
            for (int r = 0; r < 4; r++) acc[mt][nt][r] = 0.f;

    const int lr = lane & 7;
    const int lmh = (lane >> 3) & 1;
    const int lkh = lane >> 4;

    const int a_row0 = tid >> 2,  a_seg = (tid & 3) * 8;
    const int b_row0 = tid >> 4,  b_seg = (tid & 15) * 8;

#define LOAD_STAGE(st, k0)                                                     \
    {                                                                          \
        __half* As_ = smh + (st) * STG;                                        \
        __half* Bs_ = smh + (st) * STG + ASTG;                                 \
        cp16(sptr(As_ + a_row0 * 40 + a_seg),                                  \
             A + (size_t)(m0 + a_row0) * K + (k0) + a_seg);                    \
        cp16(sptr(As_ + (a_row0 + 64) * 40 + a_seg),                           \
             A + (size_t)(m0 + a_row0 + 64) * K + (k0) + a_seg);               \
        cp16(sptr(Bs_ + b_row0 * 136 + b_seg),                                 \
             Bw + (size_t)((k0) + b_row0) * N + n0 + b_seg);                   \
        cp16(sptr(Bs_ + (b_row0 + 16) * 136 + b_seg),                          \
             Bw + (size_t)((k0) + b_row0 + 16) * N + n0 + b_seg);              \
    }

    const int nk = K >> 5;
    LOAD_STAGE(0, 0);  cp_commit();
    LOAD_STAGE(1, 32); cp_commit();

    for (int it = 0; it < nk; it++) {
        const int st = it % 3;
        asm volatile("cp.async.wait_group 1;");
        __syncthreads();

        if (it + 2 < nk) {
            LOAD_STAGE((it + 2) % 3, (it + 2) * 32);
            cp_commit();
        } else {
            cp_commit();
        }

        const __half* As_ = smh + st * STG;
        const __half* Bs_ = smh + st * STG + ASTG;

#pragma unroll
        for (int ko2 = 0; ko2 < 2; ko2++) {
            const int ko = ko2 * 16;
            uint32_t af[2][4];
#pragma unroll
            for (int mt = 0; mt < 2; mt++) {
                int mrow = wm + mt * 16 + lmh * 8 + lr;
                ldm_x4(af[mt][0], af[mt][1], af[mt][2], af[mt][3],
                       sptr(As_ + mrow * 40 + ko + lkh * 8));
            }
            const int krow = ko + lmh * 8 + lr;
            uint32_t bf[2][4];
            ldm_x4t(bf[0][0], bf[0][1], bf[0][2], bf[0][3],
                    sptr(Bs_ + krow * 136 + wn + lkh * 8));
#pragma unroll
            for (int p = 0; p < 4; p++) {
                const int cur = p & 1, nxt = cur ^ 1;
                if (p < 3)
                    ldm_x4t(bf[nxt][0], bf[nxt][1], bf[nxt][2], bf[nxt][3],
                            sptr(Bs_ + krow * 136 + wn + (p + 1) * 16 + lkh * 8));
                mma16(acc[0][2 * p],     af[0], bf[cur][0], bf[cur][1]);
                mma16(acc[1][2 * p],     af[1], bf[cur][0], bf[cur][1]);
                mma16(acc[0][2 * p + 1], af[0], bf[cur][2], bf[cur][3]);
                mma16(acc[1][2 * p + 1], af[1], bf[cur][2], bf[cur][3]);
            }
        }
    }
#undef LOAD_STAGE

    float s = 0.f, s2 = 0.f;
#pragma unroll
    for (int mt = 0; mt < 2; mt++) {
        int r_lo = m0 + wm + mt * 16 + qid;
        int r_hi = r_lo + 8;
#pragma unroll
        for (int nt = 0; nt < 8; nt++) {
            int col = n0 + wn + nt * 8 + 2 * tg;
            float bx = bias[col], by = bias[col + 1];
            float v0 = acc[mt][nt][0] + bx, v1 = acc[mt][nt][1] + by;
            float v2 = acc[mt][nt][2] + bx, v3 = acc[mt][nt][3] + by;
            if (RELU) {
                v0 = fmaxf(v0, 0.f); v1 = fmaxf(v1, 0.f);
                v2 = fmaxf(v2, 0.f); v3 = fmaxf(v3, 0.f);
            }
            if (FUSE) {
                if (XHALF) {
                    __half2 xa = *(const __half2*)(Xresh + (size_t)r_lo * N + col);
                    __half2 xb = *(const __half2*)(Xresh + (size_t)r_hi * N + col);
                    v0 += __low2float(xa);  v1 += __high2float(xa);
                    v2 += __low2float(xb);  v3 += __high2float(xb);
                } else {
                    float2 xa = *(const float2*)(Xres + (size_t)r_lo * N + col);
                    float2 xb = *(const float2*)(Xres + (size_t)r_hi * N + col);
                    v0 += xa.x; v1 += xa.y; v2 += xb.x; v3 += xb.y;
                }
                s  += v0 + v1 + v2 + v3;
                s2 += v0 * v0 + v1 * v1 + v2 * v2 + v3 * v3;
            }
            *(__half2*)(Ch + (size_t)r_lo * N + col) = __floats2half2_rn(v0, v1);
            *(__half2*)(Ch + (size_t)r_hi * N + col) = __floats2half2_rn(v2, v3);
        }
    }

    if (FUSE) {
        float* rsum  = (float*)smh;
        float* rsum2 = rsum + 256;
        __syncthreads();
        rsum[tid] = s; rsum2[tid] = s2;
        __syncthreads();
        for (int off = 128; off > 0; off >>= 1) {
            if (tid < off) { rsum[tid] += rsum[tid + off]; rsum2[tid] += rsum2[tid + off]; }
            __syncthreads();
        }
        if (tid == 0) {
            int pidx = blockIdx.y * gridDim.x + blockIdx.x;
            part[2 * pidx]     = rsum[0];
            part[2 * pidx + 1] = rsum2[0];
        }
    }
}

// ---------------------------------------------------------------------------
// Single prep kernel
// ---------------------------------------------------------------------------
__global__ void __launch_bounds__(256) prep(
    const float* __restrict__ x,
    const float* __restrict__ wq, const float* __restrict__ wk,
    const float* __restrict__ wv, const float* __restrict__ wo,
    const float* __restrict__ w1, const float* __restrict__ w2,
    const float* __restrict__ bq, const float* __restrict__ bk,
    const float* __restrict__ bv,
    __half* __restrict__ xh, __half* __restrict__ wqkvh,
    __half* __restrict__ woh, __half* __restrict__ w1h,
    __half* __restrict__ w2h, float* __restrict__ bqkv)
{
    const int blk = blockIdx.x;
    const int tid = threadIdx.x;

    if (blk < 10496) {
        const float* src; __half* dst; size_t base;
        if (blk < 8192)       { src = x;  dst = xh;  base = (size_t)blk * 1024; }
        else if (blk < 8448)  { src = wo; dst = woh; base = (size_t)(blk - 8192) * 1024; }
        else if (blk < 9472)  { src = w1; dst = w1h; base = (size_t)(blk - 8448) * 1024; }
        else                  { src = w2; dst = w2h; base = (size_t)(blk - 9472) * 1024; }
        size_t i = base + (size_t)tid * 4;
        float4 v = *(const float4*)(src + i);
        *(__half2*)(dst + i)     = __floats2half2_rn(v.x, v.y);
        *(__half2*)(dst + i + 2) = __floats2half2_rn(v.z, v.w);
    } else if (blk < 11264) {
        const float* src; int off; int sb;
        if (blk < 10752)      { src = wq; off = 0;    sb = blk - 10496; }
        else if (blk < 11008) { src = wk; off = 512;  sb = blk - 10752; }
        else                  { src = wv; off = 1024; sb = blk - 11008; }
        size_t i = (size_t)sb * 1024 + (size_t)tid * 4;
        int row = (int)(i >> 9), col = (int)(i & 511);
        float4 v = *(const float4*)(src + i);
        __half* d = wqkvh + (size_t)row * QS + off + col;
        *(__half2*)(d)     = __floats2half2_rn(v.x, v.y);
        *(__half2*)(d + 2) = __floats2half2_rn(v.z, v.w);
    } else {
        for (int i = tid; i < 1536; i += 256)
            bqkv[i] = (i < 512) ? bq[i] : (i < 1024) ? bk[i - 512] : bv[i - 1024];
    }
}

// ---------------------------------------------------------------------------
// Flash attention, fp16 MMAs. grid = (S/128, B*H), block = 256 (8 warps).
// Fixed m=0 softmax; l reduced once at the end; K/P fragments via ldmatrix.
// THIS ROUND: softmax exponent via ex2.approx.f16x2 (h2exp2) — 2 exps per
// MUFU op, result already packed half2 for the P store. Scale and mask are
// folded into log2 domain; huge-negative masked args saturate to -inf in
// half -> exp2 = 0 (exact).
// ---------------------------------------------------------------------------
#define ATT_SMEM 59392
#define LOG2E 1.44269504f

__global__ void __launch_bounds__(256) attn_h(
    const __half* __restrict__ QKV, const float* __restrict__ mask,
    __half* __restrict__ O)
{
    extern __shared__ __align__(16) char smraw[];
    __half* KsB = (__half*)smraw;                  // [2][64][72]
    __half* VsB = (__half*)(smraw + 18432);        // [2][64][72]
    __half* Psb = (__half*)(smraw + 36864);        // [128][72]
    float*  Msk = (float*)(smraw + 55296);         // [1024]

    const int tid = threadIdx.x;
    const int lane = tid & 31, wid = tid >> 5;
    const int qid = lane >> 2, tg = lane & 3;
    const int lr = lane & 7, lg = lane >> 3;
    const int lmh = lg & 1, lkh = lane >> 4;
    const int qt = blockIdx.x;
    const int b  = blockIdx.y >> 3;
    const int h  = blockIdx.y & 7;
    const size_t hcol = (size_t)h * 64;
    const size_t brow = (size_t)b * Sv;

#define LOAD_KV(st, kt)                                                        \
    {                                                                          \
        _Pragma("unroll")                                                      \
        for (int i = 0; i < 2; i++) {                                          \
            int c = tid + i * 256;                                             \
            int row = c >> 3, seg = c & 7;                                     \
            size_t g = (brow + (kt) * 64 + row) * QS + hcol + seg * 8;         \
            cp16(sptr(KsB + (st) * 4608 + row * 72 + seg * 8), QKV + g + 512); \
            cp16(sptr(VsB + (st) * 4608 + row * 72 + seg * 8), QKV + g + 1024);\
        }                                                                      \
    }

    LOAD_KV(0, 0);
    cp_commit();

    // mask pre-scaled into log2 domain: mask * -1e9 * log2(e)
#pragma unroll
    for (int i = 0; i < 4; i++)
        Msk[tid + i * 256] = mask[b * Sv + tid + i * 256] * (-1e9f * LOG2E);

#pragma unroll
    for (int i = 0; i < 4; i++) {
        int c = tid + i * 256;
        int row = c >> 3, seg = c & 7;
        *(uint4*)(Psb + row * 72 + seg * 8) =
            *(const uint4*)(QKV + (brow + qt * 128 + row) * QS + hcol + seg * 8);
    }
    __syncthreads();

    const int rm = wid * 16 + qid;
    uint32_t qf[4][4];
    {
        const int qrow = wid * 16 + (lg & 1) * 8 + lr;
        const int qcol = (lg >> 1) * 8;
#pragma unroll
        for (int kk = 0; kk < 4; kk++)
            ldm_x4(qf[kk][0], qf[kk][1], qf[kk][2], qf[kk][3],
                   sptr(Psb + qrow * 72 + kk * 16 + qcol));
    }

    float l_lo = 0.f, l_hi = 0.f;
    float of[8][4];
#pragma unroll
    for (int nt = 0; nt < 8; nt++)
#pragma unroll
        for (int r = 0; r < 4; r++) of[nt][r] = 0.f;

    const int krow_off = (lg >> 1) * 8 + lr;
    const int kcol_off = (lg & 1) * 8;
    const int prow = wid * 16 + (lg & 1) * 8 + lr;
    const int pcol = (lg >> 1) * 8;
    const float C1 = 0.125f * LOG2E;   // score scale folded with log2(e)

    for (int kt = 0; kt < 16; kt++) {
        const int st = kt & 1;
        asm volatile("cp.async.wait_group 0;");
        __syncthreads();
        if (kt + 1 < 16) {
            LOAD_KV(st ^ 1, kt + 1);
            cp_commit();
        }

        float sc[8][4];
#pragma unroll
        for (int nt = 0; nt < 8; nt++)
#pragma unroll
            for (int r = 0; r < 4; r++) sc[nt][r] = 0.f;

        const __half* Kb = KsB + st * 4608;
#pragma unroll
        for (int kk = 0; kk < 4; kk++) {
#pragma unroll
            for (int np = 0; np < 4; np++) {
                uint32_t b0, b1, b2, b3;
                ldm_x4(b0, b1, b2, b3,
                       sptr(Kb + (np * 16 + krow_off) * 72 + kk * 16 + kcol_off));
                mma16(sc[2 * np],     qf[kk], b0, b1);
                mma16(sc[2 * np + 1], qf[kk], b2, b3);
            }
        }

        // softmax exponent via ex2.approx.f16x2
#pragma unroll
        for (int nt = 0; nt < 8; nt++) {
            int col = kt * 64 + nt * 8 + 2 * tg;
            float mk0 = Msk[col], mk1 = Msk[col + 1];
            __half2 a01 = __floats2half2_rn(sc[nt][0] * C1 + mk0,
                                            sc[nt][1] * C1 + mk1);
            __half2 a23 = __floats2half2_rn(sc[nt][2] * C1 + mk0,
                                            sc[nt][3] * C1 + mk1);
            __half2 e01 = h2exp2(a01);
            __half2 e23 = h2exp2(a23);
            float2 f01 = __half22float2(e01);
            float2 f23 = __half22float2(e23);
            l_lo += f01.x + f01.y;
            l_hi += f23.x + f23.y;
            *(__half2*)(Psb + rm * 72 + nt * 8 + 2 * tg)       = e01;
            *(__half2*)(Psb + (rm + 8) * 72 + nt * 8 + 2 * tg) = e23;
        }
        __syncwarp();

#pragma unroll
        for (int kk = 0; kk < 4; kk++) {
            uint32_t pa[4];
            ldm_x4(pa[0], pa[1], pa[2], pa[3],
                   sptr(Psb + prow * 72 + kk * 16 + pcol));
#pragma unroll
            for (int p = 0; p < 4; p++) {
                uint32_t b0, b1, b2, b3;
                int krow = kk * 16 + lmh * 8 + lr;
                int ncol = p * 16 + lkh * 8;
                ldm_x4t(b0, b1, b2, b3,
                        sptr(VsB + st * 4608 + krow * 72 + ncol));
                mma16(of[2 * p],     pa, b0, b1);
                mma16(of[2 * p + 1], pa, b2, b3);
            }
        }
    }
#undef LOAD_KV

    l_lo += __shfl_xor_sync(0xffffffffu, l_lo, 1);
    l_lo += __shfl_xor_sync(0xffffffffu, l_lo, 2);
    l_hi += __shfl_xor_sync(0xffffffffu, l_hi, 1);
    l_hi += __shfl_xor_sync(0xffffffffu, l_hi, 2);

    float inv_lo = 1.f / l_lo, inv_hi = 1.f / l_hi;
    size_t r_lo = brow + qt * 128 + rm;
    size_t r_hi = r_lo + 8;
#pragma unroll
    for (int nt = 0; nt < 8; nt++) {
        size_t col = hcol + nt * 8 + 2 * tg;
        *(__half2*)(O + r_lo * Dv + col) =
            __floats2half2_rn(of[nt][0] * inv_lo, of[nt][1] * inv_lo);
        *(__half2*)(O + r_hi * Dv + col) =
            __floats2half2_rn(of[nt][2] * inv_hi, of[nt][3] * inv_hi);
    }
}

// ---------------------------------------------------------------------------
// Fused LN finalize+apply (round-16 version, unchanged)
// ---------------------------------------------------------------------------
template <int OUT_HALF>
__global__ void __launch_bounds__(256) ln_apply_f(
    const __half* __restrict__ Rh, const float* __restrict__ part,
    const float* __restrict__ W, const float* __restrict__ Bb,
    float* __restrict__ out, __half* __restrict__ outh)
{
    const size_t base = (size_t)blockIdx.x * 2048;
    const int b = (int)(base >> 19);

    __shared__ float sh_mean, sh_rstd;
    if (threadIdx.x < 32) {
        float s  = part[(b * 32 + threadIdx.x) * 2 + 0];
        float s2 = part[(b * 32 + threadIdx.x) * 2 + 1];
#pragma unroll
        for (int m = 16; m; m >>= 1) {
            s  += __shfl_xor_sync(0xffffffffu, s, m);
            s2 += __shfl_xor_sync(0xffffffffu, s2, m);
        }
        if (threadIdx.x == 0) {
            float n = (float)SDv;
            float mean = s / n;
            float var  = s2 / n - mean * mean;
            sh_mean = mean;
            sh_rstd = rsqrtf(var + 1e-5f);
        }
    }
    __syncthreads();
    const float mean = sh_mean, rstd = sh_rstd;

#pragma unroll
    for (int j = 0; j < 2; j++) {
        size_t e  = base + (size_t)(threadIdx.x + j * 256) * 4;
        int sd = (int)(e & (SDv - 1));
        __half2 ra = *(const __half2*)(Rh + e);
        __half2 rb = *(const __half2*)(Rh + e + 2);
        float4 w4 = *(const float4*)(W + sd);
        float4 b4 = *(const float4*)(Bb + sd);
        float y0 = (__low2float(ra)  - mean) * rstd * w4.x + b4.x;
        float y1 = (__high2float(ra) - mean) * rstd * w4.y + b4.y;
        float y2 = (__low2float(rb)  - mean) * rstd * w4.z + b4.z;
        float y3 = (__high2float(rb) - mean) * rstd * w4.w + b4.w;
        if (OUT_HALF) {
            *(__half2*)(outh + e)     = __floats2half2_rn(y0, y1);
            *(__half2*)(outh + e + 2) = __floats2half2_rn(y2, y3);
        } else {
            *(float4*)(out + e) = make_float4(y0, y1, y2, y3);
        }
    }
}

// ---------------------------------------------------------------------------
extern "C" void kernel_launch(void* const* d_in, const int* in_sizes, int n_in,
                              void* d_out, int out_size)
{
    const float* x    = (const float*)d_in[0];
    const float* mask = (const float*)d_in[1];
    const float* wq   = (const float*)d_in[2];
    const float* bq   = (const float*)d_in[3];
    const float* wk   = (const float*)d_in[4];
    const float* bk   = (const float*)d_in[5];
    const float* wv   = (const float*)d_in[6];
    const float* bv   = (const float*)d_in[7];
    const float* wo   = (const float*)d_in[8];
    const float* bo   = (const float*)d_in[9];
    const float* w1   = (const float*)d_in[10];
    const float* b1   = (const float*)d_in[11];
    const float* w2   = (const float*)d_in[12];
    const float* b2   = (const float*)d_in[13];
    const float* ln1w = (const float*)d_in[14];
    const float* ln1b = (const float*)d_in[15];
    const float* ln2w = (const float*)d_in[16];
    const float* ln2b = (const float*)d_in[17];
    float* out = (float*)d_out;

    void* p;
    cudaGetSymbolAddress(&p, g_xh);      __half* xh    = (__half*)p;
    cudaGetSymbolAddress(&p, g_qkvh);    __half* qkvh  = (__half*)p;
    cudaGetSymbolAddress(&p, g_ctxh);    __half* ctxh  = (__half*)p;
    cudaGetSymbolAddress(&p, g_o1h);     __half* o1h   = (__half*)p;
    cudaGetSymbolAddress(&p, g_ffnh);    __half* ffnh  = (__half*)p;
    cudaGetSymbolAddress(&p, g_res1h);   __half* res1h = (__half*)p;
    cudaGetSymbolAddress(&p, g_res2h);   __half* res2h = (__half*)p;
    cudaGetSymbolAddress(&p, g_wqkvh);   __half* wqkvh = (__half*)p;
    cudaGetSymbolAddress(&p, g_woh);     __half* woh   = (__half*)p;
    cudaGetSymbolAddress(&p, g_w1h);     __half* w1h   = (__half*)p;
    cudaGetSymbolAddress(&p, g_w2h);     __half* w2h   = (__half*)p;
    cudaGetSymbolAddress(&p, g_bqkv);    float* bqkv   = (float*)p;
    cudaGetSymbolAddress(&p, g_part1);   float* part1  = (float*)p;
    cudaGetSymbolAddress(&p, g_part2);   float* part2  = (float*)p;

    cudaFuncSetAttribute(attn_h,
                         cudaFuncAttributeMaxDynamicSharedMemorySize, ATT_SMEM);
    cudaFuncSetAttribute(gemm_h<0, 0, 0>,
                         cudaFuncAttributeMaxDynamicSharedMemorySize, GEMM_SMEM);
    cudaFuncSetAttribute(gemm_h<0, 1, 0>,
                         cudaFuncAttributeMaxDynamicSharedMemorySize, GEMM_SMEM);
    cudaFuncSetAttribute(gemm_h<1, 0, 0>,
                         cudaFuncAttributeMaxDynamicSharedMemorySize, GEMM_SMEM);
    cudaFuncSetAttribute(gemm_h<0, 1, 1>,
                         cudaFuncAttributeMaxDynamicSharedMemorySize, GEMM_SMEM);

    dim3 blk(256);
    dim3 gQKV(QS / 128, BSv / 128);    // (12, 128)
    dim3 gD(Dv / 128, BSv / 128);      // (4, 128)
    dim3 gF(DFFv / 128, BSv / 128);    // (16, 128)
    dim3 gAttn(Sv / 128, Bv * 8);      // (8, 128)
    int  gApply = (BSv * Dv) / 2048;   // 4096

    prep<<<11265, 256>>>(x, wq, wk, wv, wo, w1, w2, bq, bk, bv,
                         xh, wqkvh, woh, w1h, w2h, bqkv);

    // fused QKV projection (half out, packed)
    gemm_h<0, 0, 0><<<gQKV, blk, GEMM_SMEM>>>(xh, wqkvh, bqkv, qkvh,
                                              nullptr, nullptr, nullptr, QS, Dv);

    // attention
    attn_h<<<gAttn, blk, ATT_SMEM>>>(qkvh, mask, ctxh);

    // O-projection fused with fp32-x residual + LN1 partials; res1 stored half
    gemm_h<0, 1, 0><<<gD, blk, GEMM_SMEM>>>(ctxh, woh, bo, res1h,
                                            x, nullptr, part1, Dv, Dv);
    ln_apply_f<1><<<gApply, blk>>>(res1h, part1, ln1w, ln1b, nullptr, o1h);

    // FFN1 (half out)
    gemm_h<1, 0, 0><<<gF, blk, GEMM_SMEM>>>(o1h, w1h, b1, ffnh,
                                            nullptr, nullptr, nullptr, DFFv, Dv);
    // FFN2 fused with half-o1h residual + LN2 partials; res2 stored half
    gemm_h<0, 1, 1><<<gD, blk, GEMM_SMEM>>>(ffnh, w2h, b2, res2h,
                                            nullptr, o1h, part2, Dv, DFFv);
    ln_apply_f<0><<<gApply, blk>>>(res2h, part2, ln2w, ln2b, out, nullptr);
}